// round 9
// baseline (speedup 1.0000x reference)
#include <cuda_runtime.h>
#include <cuda_bf16.h>

#define B   32
#define U   32
#define TK  64
#define TDEC 64
#define D   512
#define V   50257

// ---------------- scratch ----------------
__device__ float g_local_dec[B*D];
__device__ float g_dec_ua[B*D];
__device__ float g_dec_ta[B*D];
__device__ float g_target_out[B*D];
__device__ int   g_sel[B];
__device__ float g_logits[(long)B*V];
__device__ float g_m[B];
__device__ float g_inv_s[B];
__device__ unsigned g_hhi[B*256];   // [b][kpair] bf16x2 of h_hi
__device__ unsigned g_hlo[B*256];   // [b][kpair] bf16x2 of h_lo

// ---------------- helpers ----------------
__device__ __forceinline__ float ftanh(float x){
    float y; asm("tanh.approx.f32 %0, %1;" : "=f"(y) : "f"(x)); return y;
}
__device__ __forceinline__ float wsum(float v){
    #pragma unroll
    for (int o=16;o;o>>=1) v += __shfl_xor_sync(0xffffffffu, v, o);
    return v;
}
__device__ __forceinline__ float wmax(float v){
    #pragma unroll
    for (int o=16;o;o>>=1) v = fmaxf(v, __shfl_xor_sync(0xffffffffu, v, o));
    return v;
}
__device__ __forceinline__ unsigned smem_u32(const void* p){
    unsigned a;
    asm("{ .reg .u64 t; cvta.to.shared.u64 t, %1; cvt.u32.u64 %0, t; }" : "=r"(a) : "l"(p));
    return a;
}

// cp.async
#define CPA(dst, src) asm volatile("cp.async.cg.shared.global [%0], [%1], 16;" :: "r"(dst), "l"(src) : "memory")
#define CPC()  asm volatile("cp.async.commit_group;" ::: "memory")
#define CPW3() asm volatile("cp.async.wait_group 3;" ::: "memory")
#define CPW1() asm volatile("cp.async.wait_group 1;" ::: "memory")

// bf16 mma m16n8k16
__device__ __forceinline__ void mma16816(float* d, unsigned a0, unsigned a1,
                                         unsigned a2, unsigned a3,
                                         unsigned b0, unsigned b1){
    asm volatile("mma.sync.aligned.m16n8k16.row.col.f32.bf16.bf16.f32 "
        "{%0,%1,%2,%3}, {%4,%5,%6,%7}, {%8,%9}, {%0,%1,%2,%3};"
        : "+f"(d[0]), "+f"(d[1]), "+f"(d[2]), "+f"(d[3])
        : "r"(a0), "r"(a1), "r"(a2), "r"(a3), "r"(b0), "r"(b1));
}
__device__ __forceinline__ void cvt_hilo(float2 f, unsigned &hi, unsigned &lo){
    __nv_bfloat162 h = __float22bfloat162_rn(f);
    float2 fh = __bfloat1622float2(h);
    __nv_bfloat162 l = __float22bfloat162_rn(make_float2(f.x - fh.x, f.y - fh.y));
    hi = *(unsigned*)&h; lo = *(unsigned*)&l;
}

// ---------------- K1: layernorm ----------------
__global__ void k_ln(const float* __restrict__ tf, const float* __restrict__ g,
                     const float* __restrict__ bb){
    int b = blockIdx.x, tid = threadIdx.x;
    const float* row = tf + (b*TDEC + (TDEC-1))*D;
    float x0 = row[tid], x1 = row[tid+256];
    __shared__ float s1[256], s2[256];
    s1[tid] = x0+x1; s2[tid] = x0*x0 + x1*x1;
    __syncthreads();
    for (int o=128;o;o>>=1){
        if (tid<o){ s1[tid]+=s1[tid+o]; s2[tid]+=s2[tid+o]; }
        __syncthreads();
    }
    float mu = s1[0]*(1.0f/D);
    float var = s2[0]*(1.0f/D) - mu*mu;
    float r = rsqrtf(var + 1e-5f);
    g_local_dec[b*D+tid]     = (x0-mu)*r*g[tid]     + bb[tid];
    g_local_dec[b*D+tid+256] = (x1-mu)*r*g[tid+256] + bb[tid+256];
}

// ---------------- K2: dec projections (W rows in regs, 8 batches/block) ------
__global__ void k_proj(const float* __restrict__ ua_Wp, const float* __restrict__ ua_bp,
                       const float* __restrict__ ta_Wp, const float* __restrict__ ta_bp){
    int which = blockIdx.z;
    const float* W    = which ? ta_Wp : ua_Wp;
    const float* bias = which ? ta_bp : ua_bp;
    float* outp       = which ? g_dec_ta : g_dec_ua;
    int warp = threadIdx.x >> 5, lane = threadIdx.x & 31;
    int d = blockIdx.x*8 + warp;
    const float4* wrow = (const float4*)(W + (long)d*D);
    float4 w4[4];
    #pragma unroll
    for (int i=0;i<4;i++) w4[i] = wrow[i*32 + lane];
    float bval = bias[d];
    #pragma unroll
    for (int bi=0; bi<8; bi++){
        int b = blockIdx.y*8 + bi;
        const float4* t = (const float4*)(g_local_dec + b*D);
        float acc = 0.f;
        #pragma unroll
        for (int i=0;i<4;i++){
            float4 t4 = t[i*32 + lane];
            acc += w4[i].x*t4.x + w4[i].y*t4.y + w4[i].z*t4.z + w4[i].w*t4.w;
        }
        acc = wsum(acc);
        if (!lane) outp[b*D + d] = acc + bval;
    }
}

// ---------------- K3: utterance attention + argmax + p_gen ----------------
__global__ void k_uatt(const float* __restrict__ enc, const float* __restrict__ umask,
                       const float* __restrict__ cov, const float* __restrict__ ua_wc,
                       const float* __restrict__ ua_v, const float* __restrict__ pgen_W,
                       const float* __restrict__ pgen_b,
                       float* __restrict__ o_ucov, float* __restrict__ o_pgen,
                       float* __restrict__ o_uidx){
    int b = blockIdx.x, tid = threadIdx.x;
    int warp = tid>>5, lane = tid&31;
    __shared__ float s_scores[U], s_attn[U], s_red[256];
    float4 dec4[4], wc4[4], v4[4];
    #pragma unroll
    for (int i=0;i<4;i++){
        int d = i*128 + lane*4;
        dec4[i] = *(const float4*)(g_dec_ua + b*D + d);
        wc4[i]  = *(const float4*)(ua_wc + d);
        v4[i]   = *(const float4*)(ua_v + d);
    }
    #pragma unroll
    for (int uu=0; uu<4; uu++){
        int u = warp + uu*8;
        float c = cov[b*U + u];
        const float4* e = (const float4*)(enc + (long)(b*U + u)*D);
        float acc = 0.f;
        #pragma unroll
        for (int i=0;i<4;i++){
            float4 x = e[i*32 + lane];
            acc += ftanh(x.x + dec4[i].x + c*wc4[i].x) * v4[i].x;
            acc += ftanh(x.y + dec4[i].y + c*wc4[i].y) * v4[i].y;
            acc += ftanh(x.z + dec4[i].z + c*wc4[i].z) * v4[i].z;
            acc += ftanh(x.w + dec4[i].w + c*wc4[i].w) * v4[i].w;
        }
        acc = wsum(acc);
        if (!lane) s_scores[u] = acc;
    }
    __syncthreads();
    if (warp == 0){
        int u = lane;
        float s = s_scores[u];
        float m = wmax(s);
        float e = expf(s - m);
        float den = wsum(e);
        float a_ = (e/den) * umask[b*U+u];
        float nf = wsum(a_);
        float attn = a_ / (nf == 0.f ? 1.f : nf);
        s_attn[u] = attn;
        o_ucov[b*U+u] = cov[b*U+u] + attn;
        float bv = attn; int bi = u;
        #pragma unroll
        for (int o=16;o;o>>=1){
            float ov = __shfl_xor_sync(0xffffffffu, bv, o);
            int   oi = __shfl_xor_sync(0xffffffffu, bi, o);
            if (ov > bv || (ov == bv && oi < bi)){ bv = ov; bi = oi; }
        }
        if (!lane){ g_sel[b] = bi; o_uidx[b] = (float)bi; }
    }
    __syncthreads();
    float part = 0.f;
    #pragma unroll
    for (int j=0;j<2;j++){
        int d = tid + j*256;
        float acc = 0.f;
        #pragma unroll 8
        for (int u=0;u<U;u++) acc += s_attn[u] * enc[(long)(b*U+u)*D + d];
        part += pgen_W[d]*acc + pgen_W[D + d]*g_local_dec[b*D + d];
    }
    s_red[tid] = part;
    __syncthreads();
    for (int o=128;o;o>>=1){ if (tid<o) s_red[tid]+=s_red[tid+o]; __syncthreads(); }
    if (!tid) o_pgen[b] = 1.f/(1.f + expf(-(s_red[0] + pgen_b[0])));
}

// ---------------- K4: token attention (R5 exact: 4-stage ring, wait_group 3) --
__global__ void __launch_bounds__(256,3)
k_tatt(const float* __restrict__ tok, const float* __restrict__ tmask,
       const float* __restrict__ tcov, const float* __restrict__ ta_wc,
       const float* __restrict__ ta_v,
       float* __restrict__ o_ntc, float* __restrict__ o_tattn){
    extern __shared__ float ring[];   // 8 warps * 4 stages * 512 floats = 64KB
    __shared__ float s_scores[TK], s_attn[TK], s_cov[TK];
    int u = blockIdx.x, b = blockIdx.y;
    int tid = threadIdx.x, warp = tid>>5, lane = tid&31;
    int ub = u*B + b;
    float* wring = ring + warp*2048;
    unsigned rb = smem_u32(wring);
    const float* rowbase = tok + (long)ub*TK*D;
    if (tid < TK) s_cov[tid] = tcov[ub*TK + tid];

    float4 dec4[4], wc4[4], v4[4];
    #pragma unroll
    for (int i=0;i<4;i++){
        int d = i*128 + lane*4;
        dec4[i] = *(const float4*)(g_dec_ta + b*D + d);
        wc4[i]  = *(const float4*)(ta_wc + d);
        v4[i]   = *(const float4*)(ta_v + d);
    }
    #pragma unroll
    for (int s=0;s<3;s++){
        const float* src = rowbase + (warp*8+s)*D;
        #pragma unroll
        for (int i=0;i<4;i++)
            CPA(rb + (unsigned)(s*512 + (i*32+lane)*4)*4u, src + (i*32+lane)*4);
        CPC();
    }
    __syncthreads();   // s_cov ready
    #pragma unroll
    for (int tt=0; tt<8; tt++){
        if (tt < 5){
            const float* src = rowbase + (warp*8+tt+3)*D;
            int s = (tt+3)&3;
            #pragma unroll
            for (int i=0;i<4;i++)
                CPA(rb + (unsigned)(s*512 + (i*32+lane)*4)*4u, src + (i*32+lane)*4);
        }
        CPC();
        CPW3();
        float c = s_cov[warp*8+tt];
        const float4* xs = (const float4*)(wring + (tt&3)*512);
        float acc = 0.f;
        #pragma unroll
        for (int i=0;i<4;i++){
            float4 x = xs[i*32+lane];
            acc += ftanh(x.x + dec4[i].x + c*wc4[i].x)*v4[i].x;
            acc += ftanh(x.y + dec4[i].y + c*wc4[i].y)*v4[i].y;
            acc += ftanh(x.z + dec4[i].z + c*wc4[i].z)*v4[i].z;
            acc += ftanh(x.w + dec4[i].w + c*wc4[i].w)*v4[i].w;
        }
        acc = wsum(acc);
        if (!lane) s_scores[warp*8+tt] = acc;
    }
    __syncthreads();
    int sel = g_sel[b];
    if (warp == 0){
        float s0 = s_scores[lane], s1 = s_scores[lane+32];
        float m = wmax(fmaxf(s0,s1));
        float e0 = expf(s0-m), e1 = expf(s1-m);
        float den = wsum(e0+e1);
        float a0 = (e0/den)*tmask[ub*TK+lane];
        float a1 = (e1/den)*tmask[ub*TK+lane+32];
        float nf = wsum(a0+a1);
        float inv = 1.f/((nf==0.f)?1.f:nf);
        a0 *= inv; a1 *= inv;
        s_attn[lane] = a0; s_attn[lane+32] = a1;
        o_ntc[ub*TK+lane]    = s_cov[lane]    + a0;
        o_ntc[ub*TK+lane+32] = s_cov[lane+32] + a1;
        if (u == sel){ o_tattn[b*TK+lane] = a0; o_tattn[b*TK+lane+32] = a1; }
    }
    __syncthreads();
    if (u == sel){
        #pragma unroll
        for (int j=0;j<2;j++){
            int d = tid + j*256;
            float acc = 0.f;
            #pragma unroll 8
            for (int t=0;t<TK;t++) acc += s_attn[t]*tok[(long)ub*TK*D + t*D + d];
            g_target_out[b*D + d] = acc;
        }
    }
}

// ---------------- K5: h -> bf16 hi/lo (W1 rows in regs, 8 batches/block) -----
__global__ void k_h(const float* __restrict__ W1, const float* __restrict__ b1){
    int warp = threadIdx.x>>5, lane = threadIdx.x&31;
    int d = blockIdx.x*8 + warp;
    const float4* w = (const float4*)(W1 + (long)d*2*D);
    float4 w4[8];
    #pragma unroll
    for (int i=0;i<8;i++) w4[i] = w[i*32+lane];
    float bval = b1[d];
    #pragma unroll
    for (int bi=0; bi<8; bi++){
        int b = blockIdx.y*8 + bi;
        const float4* t0 = (const float4*)(g_target_out + b*D);
        const float4* t1 = (const float4*)(g_local_dec + b*D);
        float acc=0.f;
        #pragma unroll
        for (int i=0;i<4;i++){
            float4 x = t0[i*32+lane];
            acc += w4[i].x*x.x + w4[i].y*x.y + w4[i].z*x.z + w4[i].w*x.w;
        }
        #pragma unroll
        for (int i=0;i<4;i++){
            float4 x = t1[i*32+lane];
            acc += w4[i+4].x*x.x + w4[i+4].y*x.y + w4[i+4].z*x.z + w4[i+4].w*x.w;
        }
        acc = wsum(acc);
        if (!lane){
            float h = acc + bval;
            __nv_bfloat16 hi = __float2bfloat16(h);
            __nv_bfloat16 lo = __float2bfloat16(h - __bfloat162float(hi));
            ((__nv_bfloat16*)g_hhi)[b*512 + d] = hi;
            ((__nv_bfloat16*)g_hlo)[b*512 + d] = lo;
        }
    }
}

// ---------------- K6: vocab GEMM (mma.sync + cp.async 3-stage W pipeline) ----
#define BSTRIDE 260
#define NST 3
#define VROWF 24                 // padded floats per staged row (conflict-free)
#define VSTG (128*VROWF)         // floats per stage = 3072 (12288 B)
#define VOC_SMEM (NST*VSTG*4 + 32*BSTRIDE*8)   // 36864 + 66560 = 103424 B
__global__ void __launch_bounds__(256)
k_vocab(const float* __restrict__ W2, const float* __restrict__ b2){
    extern __shared__ char smraw[];
    float* sW = (float*)smraw;                        // NST stages of [128][24]
    uint2* sB = (uint2*)(smraw + NST*VSTG*4);         // 32 x 260
    int tid = threadIdx.x, wm = tid>>5, lane = tid&31;
    int g = lane>>2, tg = lane&3;
    long v0 = (long)blockIdx.x * 128;

    // stage B (plain stores; visible after first __syncthreads below)
    for (int i = tid; i < 32*256; i += 256){
        int n = i >> 8, kp = i & 255;
        sB[n*BSTRIDE + kp] = make_uint2(g_hhi[i], g_hlo[i]);
    }

    // W staging geometry: 512 x 16B chunks per stage, 2 per thread
    int idx0 = tid*2, idx1 = tid*2+1;
    int sr0 = idx0>>2, sc0 = idx0&3;
    int sr1 = idx1>>2, sc1 = idx1&3;
    long gv0 = v0 + sr0; if (gv0 >= V) gv0 = V-1;
    long gv1 = v0 + sr1; if (gv1 >= V) gv1 = V-1;
    const float* src0 = W2 + gv0*D + sc0*4;
    const float* src1 = W2 + gv1*D + sc1*4;
    unsigned sb = smem_u32(sW);
    unsigned dst0 = sb + (unsigned)(sr0*VROWF + sc0*4)*4u;
    unsigned dst1 = sb + (unsigned)(sr1*VROWF + sc1*4)*4u;

    // prologue: chunks 0,1 -> stages 0,1 (groups 0,1)
    #pragma unroll
    for (int s=0; s<2; s++){
        CPA(dst0 + (unsigned)s*VSTG*4u, src0 + s*16);
        CPA(dst1 + (unsigned)s*VSTG*4u, src1 + s*16);
        CPC();
    }

    int r0 = wm*16 + g, r1 = r0 + 8;
    float dd[4][4];
    #pragma unroll
    for (int nt=0;nt<4;nt++){ dd[nt][0]=dd[nt][1]=dd[nt][2]=dd[nt][3]=0.f; }

    for (int kc=0; kc<32; kc++){
        CPW1();            // groups 0..kc complete -> chunk kc resident
        __syncthreads();   // all warps done with stage (kc-1)%NST; sB visible
        if (kc+2 < 32){
            unsigned st = (unsigned)((kc+2)%NST);
            CPA(dst0 + st*VSTG*4u, src0 + (kc+2)*16);
            CPA(dst1 + st*VSTG*4u, src1 + (kc+2)*16);
        }
        CPC();             // unconditional: exactly one group per iteration

        const float* sw = sW + (kc%NST)*VSTG;
        float2 fa0 = *(const float2*)(sw + r0*VROWF + tg*2);
        float2 fa1 = *(const float2*)(sw + r1*VROWF + tg*2);
        float2 fa2 = *(const float2*)(sw + r0*VROWF + tg*2 + 8);
        float2 fa3 = *(const float2*)(sw + r1*VROWF + tg*2 + 8);

        unsigned ah0,al0,ah1,al1,ah2,al2,ah3,al3;
        cvt_hilo(fa0, ah0, al0);
        cvt_hilo(fa1, ah1, al1);
        cvt_hilo(fa2, ah2, al2);
        cvt_hilo(fa3, ah3, al3);

        int kp = kc*8 + tg;
        #pragma unroll
        for (int nt=0; nt<4; nt++){
            int nrow = (nt*8 + g)*BSTRIDE;
            uint2 b0 = sB[nrow + kp];
            uint2 b1 = sB[nrow + kp + 4];
            mma16816(dd[nt], ah0, ah1, ah2, ah3, b0.x, b1.x);  // hi*hi
            mma16816(dd[nt], al0, al1, al2, al3, b0.x, b1.x);  // lo*hi
            mma16816(dd[nt], ah0, ah1, ah2, ah3, b0.y, b1.y);  // hi*lo
        }
    }

    long rr0 = v0 + wm*16 + g;
    long rr1 = rr0 + 8;
    float bias0 = (rr0 < V) ? b2[rr0] : 0.f;
    float bias1 = (rr1 < V) ? b2[rr1] : 0.f;
    #pragma unroll
    for (int nt=0; nt<4; nt++){
        int n = nt*8 + tg*2;
        if (rr0 < V){
            g_logits[(long)n*V + rr0]     = dd[nt][0] + bias0;
            g_logits[(long)(n+1)*V + rr0] = dd[nt][1] + bias0;
        }
        if (rr1 < V){
            g_logits[(long)n*V + rr1]     = dd[nt][2] + bias1;
            g_logits[(long)(n+1)*V + rr1] = dd[nt][3] + bias1;
        }
    }
}

// ---------------- K7: softmax stats ----------------
__global__ void k_red(){
    int b = blockIdx.x, tid = threadIdx.x;
    __shared__ float sm[256];
    const float* L = g_logits + (long)b*V;
    float m = -1e30f;
    for (int v=tid; v<V; v+=256) m = fmaxf(m, L[v]);
    sm[tid]=m; __syncthreads();
    for (int o=128;o;o>>=1){ if (tid<o) sm[tid]=fmaxf(sm[tid],sm[tid+o]); __syncthreads(); }
    m = sm[0]; __syncthreads();
    float s=0.f;
    for (int v=tid; v<V; v+=256) s += expf(L[v]-m);
    sm[tid]=s; __syncthreads();
    for (int o=128;o;o>>=1){ if (tid<o) sm[tid]+=sm[tid+o]; __syncthreads(); }
    if (!tid){ g_m[b]=m; g_inv_s[b] = 1.f/sm[0]; }
}

// ---------------- K8: vocab_dist ----------------
__global__ void k_soft(float* __restrict__ o_vocab){
    long i = (long)blockIdx.x*256 + threadIdx.x;
    if (i >= (long)B*V) return;
    int b = (int)(i / V);
    o_vocab[i] = expf(g_logits[i] - g_m[b]) * g_inv_s[b];
}

// ---------------- launch ----------------
extern "C" void kernel_launch(void* const* d_in, const int* in_sizes, int n_in,
                              void* d_out, int out_size){
    const float* tf    = (const float*)d_in[0];
    const float* enc   = (const float*)d_in[2];
    const float* umask = (const float*)d_in[3];
    const float* tok   = (const float*)d_in[4];
    const float* tmask = (const float*)d_in[5];
    const float* cov   = (const float*)d_in[6];
    const float* tcov  = (const float*)d_in[7];
    const float* ua_Wp = (const float*)d_in[8];
    const float* ua_bp = (const float*)d_in[9];
    const float* ua_v  = (const float*)d_in[10];
    const float* ua_wc = (const float*)d_in[11];
    const float* ta_Wp = (const float*)d_in[12];
    const float* ta_bp = (const float*)d_in[13];
    const float* ta_v  = (const float*)d_in[14];
    const float* ta_wc = (const float*)d_in[15];
    const float* pgen_W= (const float*)d_in[16];
    const float* pgen_b= (const float*)d_in[17];
    const float* W1    = (const float*)d_in[18];
    const float* b1    = (const float*)d_in[19];
    const float* W2    = (const float*)d_in[20];
    const float* b2    = (const float*)d_in[21];
    const float* ln_g  = (const float*)d_in[22];
    const float* ln_b  = (const float*)d_in[23];

    float* out = (float*)d_out;
    float* o_vocab = out;
    float* o_tattn = o_vocab + (long)B*V;
    float* o_pgen  = o_tattn + B*TK;
    float* o_ucov  = o_pgen + B;
    float* o_ntc   = o_ucov + B*U;
    float* o_uidx  = o_ntc + (long)U*B*TK;

    cudaFuncSetAttribute(k_tatt, cudaFuncAttributeMaxDynamicSharedMemorySize, 65536);
    cudaFuncSetAttribute(k_vocab, cudaFuncAttributeMaxDynamicSharedMemorySize, VOC_SMEM);

    k_ln   <<<B, 256>>>(tf, ln_g, ln_b);
    k_proj <<<dim3(D/8, B/8, 2), 256>>>(ua_Wp, ua_bp, ta_Wp, ta_bp);
    k_uatt <<<B, 256>>>(enc, umask, cov, ua_wc, ua_v, pgen_W, pgen_b,
                        o_ucov, o_pgen, o_uidx);
    k_tatt <<<dim3(U, B), 256, 65536>>>(tok, tmask, tcov, ta_wc, ta_v, o_ntc, o_tattn);
    k_h    <<<dim3(D/8, B/8), 256>>>(W1, b1);
    k_vocab<<<(V+127)/128, 256, VOC_SMEM>>>(W2, b2);
    k_red  <<<B, 256>>>();
    k_soft <<<(int)(((long)B*V + 255)/256), 256>>>(o_vocab);
}

// round 10
// speedup vs baseline: 1.0287x; 1.0287x over previous
#include <cuda_runtime.h>
#include <cuda_bf16.h>

#define B   32
#define U   32
#define TK  64
#define TDEC 64
#define D   512
#define V   50257
#define NVBLK 393     // (V+127)/128

// ---------------- scratch ----------------
__device__ float g_local_dec[B*D];
__device__ float g_dec_ua[B*D];
__device__ float g_dec_ta[B*D];
__device__ float g_target_out[B*D];
__device__ int   g_sel[B];
__device__ float g_logits[(long)B*V];
__device__ float g_m[B];
__device__ float g_inv_s[B];
__device__ unsigned g_hhi[B*256];   // [b][kpair] bf16x2 of h_hi
__device__ unsigned g_hlo[B*256];   // [b][kpair] bf16x2 of h_lo
__device__ float g_pm[B*512];       // per-(b, vblock) partial max
__device__ float g_ps[B*512];       // per-(b, vblock) partial sumexp

// ---------------- helpers ----------------
__device__ __forceinline__ float ftanh(float x){
    float y; asm("tanh.approx.f32 %0, %1;" : "=f"(y) : "f"(x)); return y;
}
__device__ __forceinline__ float wsum(float v){
    #pragma unroll
    for (int o=16;o;o>>=1) v += __shfl_xor_sync(0xffffffffu, v, o);
    return v;
}
__device__ __forceinline__ float wmax(float v){
    #pragma unroll
    for (int o=16;o;o>>=1) v = fmaxf(v, __shfl_xor_sync(0xffffffffu, v, o));
    return v;
}
__device__ __forceinline__ unsigned smem_u32(const void* p){
    unsigned a;
    asm("{ .reg .u64 t; cvta.to.shared.u64 t, %1; cvt.u32.u64 %0, t; }" : "=r"(a) : "l"(p));
    return a;
}

// cp.async
#define CPA(dst, src) asm volatile("cp.async.cg.shared.global [%0], [%1], 16;" :: "r"(dst), "l"(src) : "memory")
#define CPC()  asm volatile("cp.async.commit_group;" ::: "memory")
#define CPW3() asm volatile("cp.async.wait_group 3;" ::: "memory")
#define CPW1() asm volatile("cp.async.wait_group 1;" ::: "memory")

// bf16 mma m16n8k16
__device__ __forceinline__ void mma16816(float* d, unsigned a0, unsigned a1,
                                         unsigned a2, unsigned a3,
                                         unsigned b0, unsigned b1){
    asm volatile("mma.sync.aligned.m16n8k16.row.col.f32.bf16.bf16.f32 "
        "{%0,%1,%2,%3}, {%4,%5,%6,%7}, {%8,%9}, {%0,%1,%2,%3};"
        : "+f"(d[0]), "+f"(d[1]), "+f"(d[2]), "+f"(d[3])
        : "r"(a0), "r"(a1), "r"(a2), "r"(a3), "r"(b0), "r"(b1));
}
__device__ __forceinline__ void cvt_hilo(float2 f, unsigned &hi, unsigned &lo){
    __nv_bfloat162 h = __float22bfloat162_rn(f);
    float2 fh = __bfloat1622float2(h);
    __nv_bfloat162 l = __float22bfloat162_rn(make_float2(f.x - fh.x, f.y - fh.y));
    hi = *(unsigned*)&h; lo = *(unsigned*)&l;
}

// ---------------- K1: layernorm ----------------
__global__ void k_ln(const float* __restrict__ tf, const float* __restrict__ g,
                     const float* __restrict__ bb){
    int b = blockIdx.x, tid = threadIdx.x;
    const float* row = tf + (b*TDEC + (TDEC-1))*D;
    float x0 = row[tid], x1 = row[tid+256];
    __shared__ float s1[256], s2[256];
    s1[tid] = x0+x1; s2[tid] = x0*x0 + x1*x1;
    __syncthreads();
    for (int o=128;o;o>>=1){
        if (tid<o){ s1[tid]+=s1[tid+o]; s2[tid]+=s2[tid+o]; }
        __syncthreads();
    }
    float mu = s1[0]*(1.0f/D);
    float var = s2[0]*(1.0f/D) - mu*mu;
    float r = rsqrtf(var + 1e-5f);
    g_local_dec[b*D+tid]     = (x0-mu)*r*g[tid]     + bb[tid];
    g_local_dec[b*D+tid+256] = (x1-mu)*r*g[tid+256] + bb[tid+256];
}

// ---------------- K2: dec projections (W rows in regs, 8 batches/block) ------
__global__ void k_proj(const float* __restrict__ ua_Wp, const float* __restrict__ ua_bp,
                       const float* __restrict__ ta_Wp, const float* __restrict__ ta_bp){
    int which = blockIdx.z;
    const float* W    = which ? ta_Wp : ua_Wp;
    const float* bias = which ? ta_bp : ua_bp;
    float* outp       = which ? g_dec_ta : g_dec_ua;
    int warp = threadIdx.x >> 5, lane = threadIdx.x & 31;
    int d = blockIdx.x*8 + warp;
    const float4* wrow = (const float4*)(W + (long)d*D);
    float4 w4[4];
    #pragma unroll
    for (int i=0;i<4;i++) w4[i] = wrow[i*32 + lane];
    float bval = bias[d];
    #pragma unroll
    for (int bi=0; bi<8; bi++){
        int b = blockIdx.y*8 + bi;
        const float4* t = (const float4*)(g_local_dec + b*D);
        float acc = 0.f;
        #pragma unroll
        for (int i=0;i<4;i++){
            float4 t4 = t[i*32 + lane];
            acc += w4[i].x*t4.x + w4[i].y*t4.y + w4[i].z*t4.z + w4[i].w*t4.w;
        }
        acc = wsum(acc);
        if (!lane) outp[b*D + d] = acc + bval;
    }
}

// ---------------- K3: utterance attention + argmax + p_gen ----------------
__global__ void k_uatt(const float* __restrict__ enc, const float* __restrict__ umask,
                       const float* __restrict__ cov, const float* __restrict__ ua_wc,
                       const float* __restrict__ ua_v, const float* __restrict__ pgen_W,
                       const float* __restrict__ pgen_b,
                       float* __restrict__ o_ucov, float* __restrict__ o_pgen,
                       float* __restrict__ o_uidx){
    int b = blockIdx.x, tid = threadIdx.x;
    int warp = tid>>5, lane = tid&31;
    __shared__ float s_scores[U], s_attn[U], s_red[256];
    float4 dec4[4], wc4[4], v4[4];
    #pragma unroll
    for (int i=0;i<4;i++){
        int d = i*128 + lane*4;
        dec4[i] = *(const float4*)(g_dec_ua + b*D + d);
        wc4[i]  = *(const float4*)(ua_wc + d);
        v4[i]   = *(const float4*)(ua_v + d);
    }
    #pragma unroll
    for (int uu=0; uu<4; uu++){
        int u = warp + uu*8;
        float c = cov[b*U + u];
        const float4* e = (const float4*)(enc + (long)(b*U + u)*D);
        float acc = 0.f;
        #pragma unroll
        for (int i=0;i<4;i++){
            float4 x = e[i*32 + lane];
            acc += ftanh(x.x + dec4[i].x + c*wc4[i].x) * v4[i].x;
            acc += ftanh(x.y + dec4[i].y + c*wc4[i].y) * v4[i].y;
            acc += ftanh(x.z + dec4[i].z + c*wc4[i].z) * v4[i].z;
            acc += ftanh(x.w + dec4[i].w + c*wc4[i].w) * v4[i].w;
        }
        acc = wsum(acc);
        if (!lane) s_scores[u] = acc;
    }
    __syncthreads();
    if (warp == 0){
        int u = lane;
        float s = s_scores[u];
        float m = wmax(s);
        float e = expf(s - m);
        float den = wsum(e);
        float a_ = (e/den) * umask[b*U+u];
        float nf = wsum(a_);
        float attn = a_ / (nf == 0.f ? 1.f : nf);
        s_attn[u] = attn;
        o_ucov[b*U+u] = cov[b*U+u] + attn;
        float bv = attn; int bi = u;
        #pragma unroll
        for (int o=16;o;o>>=1){
            float ov = __shfl_xor_sync(0xffffffffu, bv, o);
            int   oi = __shfl_xor_sync(0xffffffffu, bi, o);
            if (ov > bv || (ov == bv && oi < bi)){ bv = ov; bi = oi; }
        }
        if (!lane){ g_sel[b] = bi; o_uidx[b] = (float)bi; }
    }
    __syncthreads();
    float part = 0.f;
    #pragma unroll
    for (int j=0;j<2;j++){
        int d = tid + j*256;
        float acc = 0.f;
        #pragma unroll 8
        for (int u=0;u<U;u++) acc += s_attn[u] * enc[(long)(b*U+u)*D + d];
        part += pgen_W[d]*acc + pgen_W[D + d]*g_local_dec[b*D + d];
    }
    s_red[tid] = part;
    __syncthreads();
    for (int o=128;o;o>>=1){ if (tid<o) s_red[tid]+=s_red[tid+o]; __syncthreads(); }
    if (!tid) o_pgen[b] = 1.f/(1.f + expf(-(s_red[0] + pgen_b[0])));
}

// ---------------- K4: token attention (R5 exact: 4-stage ring, wait_group 3) --
__global__ void __launch_bounds__(256,3)
k_tatt(const float* __restrict__ tok, const float* __restrict__ tmask,
       const float* __restrict__ tcov, const float* __restrict__ ta_wc,
       const float* __restrict__ ta_v,
       float* __restrict__ o_ntc, float* __restrict__ o_tattn){
    extern __shared__ float ring[];   // 8 warps * 4 stages * 512 floats = 64KB
    __shared__ float s_scores[TK], s_attn[TK], s_cov[TK];
    int u = blockIdx.x, b = blockIdx.y;
    int tid = threadIdx.x, warp = tid>>5, lane = tid&31;
    int ub = u*B + b;
    float* wring = ring + warp*2048;
    unsigned rb = smem_u32(wring);
    const float* rowbase = tok + (long)ub*TK*D;
    if (tid < TK) s_cov[tid] = tcov[ub*TK + tid];

    float4 dec4[4], wc4[4], v4[4];
    #pragma unroll
    for (int i=0;i<4;i++){
        int d = i*128 + lane*4;
        dec4[i] = *(const float4*)(g_dec_ta + b*D + d);
        wc4[i]  = *(const float4*)(ta_wc + d);
        v4[i]   = *(const float4*)(ta_v + d);
    }
    #pragma unroll
    for (int s=0;s<3;s++){
        const float* src = rowbase + (warp*8+s)*D;
        #pragma unroll
        for (int i=0;i<4;i++)
            CPA(rb + (unsigned)(s*512 + (i*32+lane)*4)*4u, src + (i*32+lane)*4);
        CPC();
    }
    __syncthreads();   // s_cov ready
    #pragma unroll
    for (int tt=0; tt<8; tt++){
        if (tt < 5){
            const float* src = rowbase + (warp*8+tt+3)*D;
            int s = (tt+3)&3;
            #pragma unroll
            for (int i=0;i<4;i++)
                CPA(rb + (unsigned)(s*512 + (i*32+lane)*4)*4u, src + (i*32+lane)*4);
        }
        CPC();
        CPW3();
        float c = s_cov[warp*8+tt];
        const float4* xs = (const float4*)(wring + (tt&3)*512);
        float acc = 0.f;
        #pragma unroll
        for (int i=0;i<4;i++){
            float4 x = xs[i*32+lane];
            acc += ftanh(x.x + dec4[i].x + c*wc4[i].x)*v4[i].x;
            acc += ftanh(x.y + dec4[i].y + c*wc4[i].y)*v4[i].y;
            acc += ftanh(x.z + dec4[i].z + c*wc4[i].z)*v4[i].z;
            acc += ftanh(x.w + dec4[i].w + c*wc4[i].w)*v4[i].w;
        }
        acc = wsum(acc);
        if (!lane) s_scores[warp*8+tt] = acc;
    }
    __syncthreads();
    int sel = g_sel[b];
    if (warp == 0){
        float s0 = s_scores[lane], s1 = s_scores[lane+32];
        float m = wmax(fmaxf(s0,s1));
        float e0 = expf(s0-m), e1 = expf(s1-m);
        float den = wsum(e0+e1);
        float a0 = (e0/den)*tmask[ub*TK+lane];
        float a1 = (e1/den)*tmask[ub*TK+lane+32];
        float nf = wsum(a0+a1);
        float inv = 1.f/((nf==0.f)?1.f:nf);
        a0 *= inv; a1 *= inv;
        s_attn[lane] = a0; s_attn[lane+32] = a1;
        o_ntc[ub*TK+lane]    = s_cov[lane]    + a0;
        o_ntc[ub*TK+lane+32] = s_cov[lane+32] + a1;
        if (u == sel){ o_tattn[b*TK+lane] = a0; o_tattn[b*TK+lane+32] = a1; }
    }
    __syncthreads();
    if (u == sel){
        #pragma unroll
        for (int j=0;j<2;j++){
            int d = tid + j*256;
            float acc = 0.f;
            #pragma unroll 8
            for (int t=0;t<TK;t++) acc += s_attn[t]*tok[(long)ub*TK*D + t*D + d];
            g_target_out[b*D + d] = acc;
        }
    }
}

// ---------------- K5: h -> bf16 hi/lo (W1 rows in regs, 8 batches/block) -----
__global__ void k_h(const float* __restrict__ W1, const float* __restrict__ b1){
    int warp = threadIdx.x>>5, lane = threadIdx.x&31;
    int d = blockIdx.x*8 + warp;
    const float4* w = (const float4*)(W1 + (long)d*2*D);
    float4 w4[8];
    #pragma unroll
    for (int i=0;i<8;i++) w4[i] = w[i*32+lane];
    float bval = b1[d];
    #pragma unroll
    for (int bi=0; bi<8; bi++){
        int b = blockIdx.y*8 + bi;
        const float4* t0 = (const float4*)(g_target_out + b*D);
        const float4* t1 = (const float4*)(g_local_dec + b*D);
        float acc=0.f;
        #pragma unroll
        for (int i=0;i<4;i++){
            float4 x = t0[i*32+lane];
            acc += w4[i].x*x.x + w4[i].y*x.y + w4[i].z*x.z + w4[i].w*x.w;
        }
        #pragma unroll
        for (int i=0;i<4;i++){
            float4 x = t1[i*32+lane];
            acc += w4[i+4].x*x.x + w4[i+4].y*x.y + w4[i+4].z*x.z + w4[i+4].w*x.w;
        }
        acc = wsum(acc);
        if (!lane){
            float h = acc + bval;
            __nv_bfloat16 hi = __float2bfloat16(h);
            __nv_bfloat16 lo = __float2bfloat16(h - __bfloat162float(hi));
            ((__nv_bfloat16*)g_hhi)[b*512 + d] = hi;
            ((__nv_bfloat16*)g_hlo)[b*512 + d] = lo;
        }
    }
}

// ---------------- K6: vocab GEMM + fused partial softmax stats ----------------
#define BSTRIDE 260
#define NST 3
#define VROWF 24                 // padded floats per staged row (conflict-free)
#define VSTG (128*VROWF)         // floats per stage = 3072 (12288 B)
#define VOC_SMEM (NST*VSTG*4 + 32*BSTRIDE*8)   // 36864 + 66560 = 103424 B
__global__ void __launch_bounds__(256)
k_vocab(const float* __restrict__ W2, const float* __restrict__ b2){
    extern __shared__ char smraw[];
    float* sW = (float*)smraw;                        // NST stages of [128][24]
    uint2* sB = (uint2*)(smraw + NST*VSTG*4);         // 32 x 260
    __shared__ float sm_m[8][32], sm_s[8][32];
    int tid = threadIdx.x, wm = tid>>5, lane = tid&31;
    int g = lane>>2, tg = lane&3;
    long v0 = (long)blockIdx.x * 128;

    // stage B (plain stores; visible after first __syncthreads below)
    for (int i = tid; i < 32*256; i += 256){
        int n = i >> 8, kp = i & 255;
        sB[n*BSTRIDE + kp] = make_uint2(g_hhi[i], g_hlo[i]);
    }

    // W staging geometry: 512 x 16B chunks per stage, 2 per thread
    int idx0 = tid*2, idx1 = tid*2+1;
    int sr0 = idx0>>2, sc0 = idx0&3;
    int sr1 = idx1>>2, sc1 = idx1&3;
    long gv0 = v0 + sr0; if (gv0 >= V) gv0 = V-1;
    long gv1 = v0 + sr1; if (gv1 >= V) gv1 = V-1;
    const float* src0 = W2 + gv0*D + sc0*4;
    const float* src1 = W2 + gv1*D + sc1*4;
    unsigned sb = smem_u32(sW);
    unsigned dst0 = sb + (unsigned)(sr0*VROWF + sc0*4)*4u;
    unsigned dst1 = sb + (unsigned)(sr1*VROWF + sc1*4)*4u;

    // prologue: chunks 0,1 -> stages 0,1 (groups 0,1)
    #pragma unroll
    for (int s=0; s<2; s++){
        CPA(dst0 + (unsigned)s*VSTG*4u, src0 + s*16);
        CPA(dst1 + (unsigned)s*VSTG*4u, src1 + s*16);
        CPC();
    }

    int r0 = wm*16 + g, r1 = r0 + 8;
    float dd[4][4];
    #pragma unroll
    for (int nt=0;nt<4;nt++){ dd[nt][0]=dd[nt][1]=dd[nt][2]=dd[nt][3]=0.f; }

    for (int kc=0; kc<32; kc++){
        CPW1();            // groups 0..kc complete -> chunk kc resident
        __syncthreads();   // all warps done with stage (kc-1)%NST; sB visible
        if (kc+2 < 32){
            unsigned st = (unsigned)((kc+2)%NST);
            CPA(dst0 + st*VSTG*4u, src0 + (kc+2)*16);
            CPA(dst1 + st*VSTG*4u, src1 + (kc+2)*16);
        }
        CPC();             // unconditional: exactly one group per iteration

        const float* sw = sW + (kc%NST)*VSTG;
        float2 fa0 = *(const float2*)(sw + r0*VROWF + tg*2);
        float2 fa1 = *(const float2*)(sw + r1*VROWF + tg*2);
        float2 fa2 = *(const float2*)(sw + r0*VROWF + tg*2 + 8);
        float2 fa3 = *(const float2*)(sw + r1*VROWF + tg*2 + 8);

        unsigned ah0,al0,ah1,al1,ah2,al2,ah3,al3;
        cvt_hilo(fa0, ah0, al0);
        cvt_hilo(fa1, ah1, al1);
        cvt_hilo(fa2, ah2, al2);
        cvt_hilo(fa3, ah3, al3);

        int kp = kc*8 + tg;
        #pragma unroll
        for (int nt=0; nt<4; nt++){
            int nrow = (nt*8 + g)*BSTRIDE;
            uint2 b0 = sB[nrow + kp];
            uint2 b1 = sB[nrow + kp + 4];
            mma16816(dd[nt], ah0, ah1, ah2, ah3, b0.x, b1.x);  // hi*hi
            mma16816(dd[nt], al0, al1, al2, al3, b0.x, b1.x);  // lo*hi
            mma16816(dd[nt], ah0, ah1, ah2, ah3, b0.y, b1.y);  // hi*lo
        }
    }

    long rr0 = v0 + wm*16 + g;
    long rr1 = rr0 + 8;
    bool ok0 = (rr0 < V), ok1 = (rr1 < V);
    float bias0 = ok0 ? b2[rr0] : 0.f;
    float bias1 = ok1 ? b2[rr1] : 0.f;
    #pragma unroll
    for (int nt=0; nt<4; nt++){
        int n = nt*8 + tg*2;
        if (ok0){
            g_logits[(long)n*V + rr0]     = dd[nt][0] + bias0;
            g_logits[(long)(n+1)*V + rr0] = dd[nt][1] + bias0;
        }
        if (ok1){
            g_logits[(long)n*V + rr1]     = dd[nt][2] + bias1;
            g_logits[(long)(n+1)*V + rr1] = dd[nt][3] + bias1;
        }
    }

    // ---- fused partial softmax stats: per (block, n) (max, sumexp) ----
    #pragma unroll
    for (int nt=0; nt<4; nt++){
        #pragma unroll
        for (int p=0; p<2; p++){
            float x0 = ok0 ? dd[nt][p]   + bias0 : -1e30f;
            float x1 = ok1 ? dd[nt][p+2] + bias1 : -1e30f;
            float m = fmaxf(x0, x1);
            #pragma unroll
            for (int o=4; o<32; o<<=1) m = fmaxf(m, __shfl_xor_sync(0xffffffffu, m, o));
            float s = (ok0 ? expf(x0 - m) : 0.f) + (ok1 ? expf(x1 - m) : 0.f);
            #pragma unroll
            for (int o=4; o<32; o<<=1) s += __shfl_xor_sync(0xffffffffu, s, o);
            if (g == 0){
                int n = nt*8 + tg*2 + p;
                sm_m[wm][n] = m;
                sm_s[wm][n] = s;
            }
        }
    }
    __syncthreads();
    if (wm == 0){
        float M = -1e30f;
        #pragma unroll
        for (int w=0; w<8; w++) M = fmaxf(M, sm_m[w][lane]);
        float S = 0.f;
        #pragma unroll
        for (int w=0; w<8; w++) S += sm_s[w][lane] * expf(sm_m[w][lane] - M);
        g_pm[(long)lane*512 + blockIdx.x] = M;
        g_ps[(long)lane*512 + blockIdx.x] = S;
    }
}

// ---------------- K7: combine partial stats (tiny) ----------------
__global__ void k_red(){
    int b = blockIdx.x, tid = threadIdx.x;
    __shared__ float smm[256], sms[256];
    float m0 = (tid      < NVBLK) ? g_pm[(long)b*512 + tid]       : -1e30f;
    float s0 = (tid      < NVBLK) ? g_ps[(long)b*512 + tid]       : 0.f;
    float m1 = (tid+256  < NVBLK) ? g_pm[(long)b*512 + tid + 256] : -1e30f;
    float s1 = (tid+256  < NVBLK) ? g_ps[(long)b*512 + tid + 256] : 0.f;
    float m = fmaxf(m0, m1);
    smm[tid] = m;
    __syncthreads();
    for (int o=128;o;o>>=1){ if (tid<o) smm[tid]=fmaxf(smm[tid],smm[tid+o]); __syncthreads(); }
    float M = smm[0];
    __syncthreads();
    float s = s0*expf(m0 - M) + s1*expf(m1 - M);
    sms[tid] = s;
    __syncthreads();
    for (int o=128;o;o>>=1){ if (tid<o) sms[tid]+=sms[tid+o]; __syncthreads(); }
    if (!tid){ g_m[b] = M; g_inv_s[b] = 1.f/sms[0]; }
}

// ---------------- K8: vocab_dist ----------------
__global__ void k_soft(float* __restrict__ o_vocab){
    long i = (long)blockIdx.x*256 + threadIdx.x;
    if (i >= (long)B*V) return;
    int b = (int)(i / V);
    o_vocab[i] = expf(g_logits[i] - g_m[b]) * g_inv_s[b];
}

// ---------------- launch ----------------
extern "C" void kernel_launch(void* const* d_in, const int* in_sizes, int n_in,
                              void* d_out, int out_size){
    const float* tf    = (const float*)d_in[0];
    const float* enc   = (const float*)d_in[2];
    const float* umask = (const float*)d_in[3];
    const float* tok   = (const float*)d_in[4];
    const float* tmask = (const float*)d_in[5];
    const float* cov   = (const float*)d_in[6];
    const float* tcov  = (const float*)d_in[7];
    const float* ua_Wp = (const float*)d_in[8];
    const float* ua_bp = (const float*)d_in[9];
    const float* ua_v  = (const float*)d_in[10];
    const float* ua_wc = (const float*)d_in[11];
    const float* ta_Wp = (const float*)d_in[12];
    const float* ta_bp = (const float*)d_in[13];
    const float* ta_v  = (const float*)d_in[14];
    const float* ta_wc = (const float*)d_in[15];
    const float* pgen_W= (const float*)d_in[16];
    const float* pgen_b= (const float*)d_in[17];
    const float* W1    = (const float*)d_in[18];
    const float* b1    = (const float*)d_in[19];
    const float* W2    = (const float*)d_in[20];
    const float* b2    = (const float*)d_in[21];
    const float* ln_g  = (const float*)d_in[22];
    const float* ln_b  = (const float*)d_in[23];

    float* out = (float*)d_out;
    float* o_vocab = out;
    float* o_tattn = o_vocab + (long)B*V;
    float* o_pgen  = o_tattn + B*TK;
    float* o_ucov  = o_pgen + B;
    float* o_ntc   = o_ucov + B*U;
    float* o_uidx  = o_ntc + (long)U*B*TK;

    cudaFuncSetAttribute(k_tatt, cudaFuncAttributeMaxDynamicSharedMemorySize, 65536);
    cudaFuncSetAttribute(k_vocab, cudaFuncAttributeMaxDynamicSharedMemorySize, VOC_SMEM);

    k_ln   <<<B, 256>>>(tf, ln_g, ln_b);
    k_proj <<<dim3(D/8, B/8, 2), 256>>>(ua_Wp, ua_bp, ta_Wp, ta_bp);
    k_uatt <<<B, 256>>>(enc, umask, cov, ua_wc, ua_v, pgen_W, pgen_b,
                        o_ucov, o_pgen, o_uidx);
    k_tatt <<<dim3(U, B), 256, 65536>>>(tok, tmask, tcov, ta_wc, ta_v, o_ntc, o_tattn);
    k_h    <<<dim3(D/8, B/8), 256>>>(W1, b1);
    k_vocab<<<NVBLK, 256, VOC_SMEM>>>(W2, b2);
    k_red  <<<B, 256>>>();
    k_soft <<<(int)(((long)B*V + 255)/256), 256>>>(o_vocab);
}

// round 11
// speedup vs baseline: 1.0851x; 1.0548x over previous
#include <cuda_runtime.h>
#include <cuda_bf16.h>

#define B   32
#define U   32
#define TK  64
#define TDEC 64
#define D   512
#define V   50257
#define NVBLK 393     // (V+127)/128

// ---------------- scratch ----------------
__device__ float g_local_dec[B*D];
__device__ float g_dec_ua[B*D];
__device__ float g_dec_ta[B*D];
__device__ float g_target_out[B*D];
__device__ int   g_sel[B];
__device__ float g_logits[(long)B*V];
__device__ float g_m[B];
__device__ float g_inv_s[B];
__device__ unsigned g_hhi[B*256];   // [b][kpair] bf16x2 of h_hi
__device__ unsigned g_hlo[B*256];   // [b][kpair] bf16x2 of h_lo
__device__ float g_pm[B*512];       // per-(b, vblock) partial max
__device__ float g_ps[B*512];       // per-(b, vblock) partial sumexp

// ---------------- helpers ----------------
__device__ __forceinline__ float ftanh(float x){
    float y; asm("tanh.approx.f32 %0, %1;" : "=f"(y) : "f"(x)); return y;
}
__device__ __forceinline__ float wsum(float v){
    #pragma unroll
    for (int o=16;o;o>>=1) v += __shfl_xor_sync(0xffffffffu, v, o);
    return v;
}
__device__ __forceinline__ float wmax(float v){
    #pragma unroll
    for (int o=16;o;o>>=1) v = fmaxf(v, __shfl_xor_sync(0xffffffffu, v, o));
    return v;
}
__device__ __forceinline__ unsigned smem_u32(const void* p){
    unsigned a;
    asm("{ .reg .u64 t; cvta.to.shared.u64 t, %1; cvt.u32.u64 %0, t; }" : "=r"(a) : "l"(p));
    return a;
}

// cp.async
#define CPA(dst, src) asm volatile("cp.async.cg.shared.global [%0], [%1], 16;" :: "r"(dst), "l"(src) : "memory")
#define CPC()  asm volatile("cp.async.commit_group;" ::: "memory")
#define CPW3() asm volatile("cp.async.wait_group 3;" ::: "memory")
#define CPW1() asm volatile("cp.async.wait_group 1;" ::: "memory")

// bf16 mma m16n8k16
__device__ __forceinline__ void mma16816(float* d, unsigned a0, unsigned a1,
                                         unsigned a2, unsigned a3,
                                         unsigned b0, unsigned b1){
    asm volatile("mma.sync.aligned.m16n8k16.row.col.f32.bf16.bf16.f32 "
        "{%0,%1,%2,%3}, {%4,%5,%6,%7}, {%8,%9}, {%0,%1,%2,%3};"
        : "+f"(d[0]), "+f"(d[1]), "+f"(d[2]), "+f"(d[3])
        : "r"(a0), "r"(a1), "r"(a2), "r"(a3), "r"(b0), "r"(b1));
}
__device__ __forceinline__ void cvt_hilo(float2 f, unsigned &hi, unsigned &lo){
    __nv_bfloat162 h = __float22bfloat162_rn(f);
    float2 fh = __bfloat1622float2(h);
    __nv_bfloat162 l = __float22bfloat162_rn(make_float2(f.x - fh.x, f.y - fh.y));
    hi = *(unsigned*)&h; lo = *(unsigned*)&l;
}

// ---------------- K1: layernorm ----------------
__global__ void k_ln(const float* __restrict__ tf, const float* __restrict__ g,
                     const float* __restrict__ bb){
    int b = blockIdx.x, tid = threadIdx.x;
    const float* row = tf + (b*TDEC + (TDEC-1))*D;
    float x0 = row[tid], x1 = row[tid+256];
    __shared__ float s1[256], s2[256];
    s1[tid] = x0+x1; s2[tid] = x0*x0 + x1*x1;
    __syncthreads();
    for (int o=128;o;o>>=1){
        if (tid<o){ s1[tid]+=s1[tid+o]; s2[tid]+=s2[tid+o]; }
        __syncthreads();
    }
    float mu = s1[0]*(1.0f/D);
    float var = s2[0]*(1.0f/D) - mu*mu;
    float r = rsqrtf(var + 1e-5f);
    g_local_dec[b*D+tid]     = (x0-mu)*r*g[tid]     + bb[tid];
    g_local_dec[b*D+tid+256] = (x1-mu)*r*g[tid+256] + bb[tid+256];
}

// ---------------- K2: dec projections (W rows in regs, 8 batches/block) ------
__global__ void k_proj(const float* __restrict__ ua_Wp, const float* __restrict__ ua_bp,
                       const float* __restrict__ ta_Wp, const float* __restrict__ ta_bp){
    int which = blockIdx.z;
    const float* W    = which ? ta_Wp : ua_Wp;
    const float* bias = which ? ta_bp : ua_bp;
    float* outp       = which ? g_dec_ta : g_dec_ua;
    int warp = threadIdx.x >> 5, lane = threadIdx.x & 31;
    int d = blockIdx.x*8 + warp;
    const float4* wrow = (const float4*)(W + (long)d*D);
    float4 w4[4];
    #pragma unroll
    for (int i=0;i<4;i++) w4[i] = wrow[i*32 + lane];
    float bval = bias[d];
    #pragma unroll
    for (int bi=0; bi<8; bi++){
        int b = blockIdx.y*8 + bi;
        const float4* t = (const float4*)(g_local_dec + b*D);
        float acc = 0.f;
        #pragma unroll
        for (int i=0;i<4;i++){
            float4 t4 = t[i*32 + lane];
            acc += w4[i].x*t4.x + w4[i].y*t4.y + w4[i].z*t4.z + w4[i].w*t4.w;
        }
        acc = wsum(acc);
        if (!lane) outp[b*D + d] = acc + bval;
    }
}

// ---------------- K3: utterance attention + argmax + p_gen ----------------
__global__ void k_uatt(const float* __restrict__ enc, const float* __restrict__ umask,
                       const float* __restrict__ cov, const float* __restrict__ ua_wc,
                       const float* __restrict__ ua_v, const float* __restrict__ pgen_W,
                       const float* __restrict__ pgen_b,
                       float* __restrict__ o_ucov, float* __restrict__ o_pgen,
                       float* __restrict__ o_uidx){
    int b = blockIdx.x, tid = threadIdx.x;
    int warp = tid>>5, lane = tid&31;
    __shared__ float s_scores[U], s_attn[U], s_red[256];
    float4 dec4[4], wc4[4], v4[4];
    #pragma unroll
    for (int i=0;i<4;i++){
        int d = i*128 + lane*4;
        dec4[i] = *(const float4*)(g_dec_ua + b*D + d);
        wc4[i]  = *(const float4*)(ua_wc + d);
        v4[i]   = *(const float4*)(ua_v + d);
    }
    #pragma unroll
    for (int uu=0; uu<4; uu++){
        int u = warp + uu*8;
        float c = cov[b*U + u];
        const float4* e = (const float4*)(enc + (long)(b*U + u)*D);
        float acc = 0.f;
        #pragma unroll
        for (int i=0;i<4;i++){
            float4 x = e[i*32 + lane];
            acc += ftanh(x.x + dec4[i].x + c*wc4[i].x) * v4[i].x;
            acc += ftanh(x.y + dec4[i].y + c*wc4[i].y) * v4[i].y;
            acc += ftanh(x.z + dec4[i].z + c*wc4[i].z) * v4[i].z;
            acc += ftanh(x.w + dec4[i].w + c*wc4[i].w) * v4[i].w;
        }
        acc = wsum(acc);
        if (!lane) s_scores[u] = acc;
    }
    __syncthreads();
    if (warp == 0){
        int u = lane;
        float s = s_scores[u];
        float m = wmax(s);
        float e = expf(s - m);
        float den = wsum(e);
        float a_ = (e/den) * umask[b*U+u];
        float nf = wsum(a_);
        float attn = a_ / (nf == 0.f ? 1.f : nf);
        s_attn[u] = attn;
        o_ucov[b*U+u] = cov[b*U+u] + attn;
        float bv = attn; int bi = u;
        #pragma unroll
        for (int o=16;o;o>>=1){
            float ov = __shfl_xor_sync(0xffffffffu, bv, o);
            int   oi = __shfl_xor_sync(0xffffffffu, bi, o);
            if (ov > bv || (ov == bv && oi < bi)){ bv = ov; bi = oi; }
        }
        if (!lane){ g_sel[b] = bi; o_uidx[b] = (float)bi; }
    }
    __syncthreads();
    float part = 0.f;
    #pragma unroll
    for (int j=0;j<2;j++){
        int d = tid + j*256;
        float acc = 0.f;
        #pragma unroll 8
        for (int u=0;u<U;u++) acc += s_attn[u] * enc[(long)(b*U+u)*D + d];
        part += pgen_W[d]*acc + pgen_W[D + d]*g_local_dec[b*D + d];
    }
    s_red[tid] = part;
    __syncthreads();
    for (int o=128;o;o>>=1){ if (tid<o) s_red[tid]+=s_red[tid+o]; __syncthreads(); }
    if (!tid) o_pgen[b] = 1.f/(1.f + expf(-(s_red[0] + pgen_b[0])));
}

// ---------------- K4: token attention (R5 exact: 4-stage ring, wait_group 3) --
__global__ void __launch_bounds__(256,3)
k_tatt(const float* __restrict__ tok, const float* __restrict__ tmask,
       const float* __restrict__ tcov, const float* __restrict__ ta_wc,
       const float* __restrict__ ta_v,
       float* __restrict__ o_ntc, float* __restrict__ o_tattn){
    extern __shared__ float ring[];   // 8 warps * 4 stages * 512 floats = 64KB
    __shared__ float s_scores[TK], s_attn[TK], s_cov[TK];
    int u = blockIdx.x, b = blockIdx.y;
    int tid = threadIdx.x, warp = tid>>5, lane = tid&31;
    int ub = u*B + b;
    float* wring = ring + warp*2048;
    unsigned rb = smem_u32(wring);
    const float* rowbase = tok + (long)ub*TK*D;
    if (tid < TK) s_cov[tid] = tcov[ub*TK + tid];

    float4 dec4[4], wc4[4], v4[4];
    #pragma unroll
    for (int i=0;i<4;i++){
        int d = i*128 + lane*4;
        dec4[i] = *(const float4*)(g_dec_ta + b*D + d);
        wc4[i]  = *(const float4*)(ta_wc + d);
        v4[i]   = *(const float4*)(ta_v + d);
    }
    #pragma unroll
    for (int s=0;s<3;s++){
        const float* src = rowbase + (warp*8+s)*D;
        #pragma unroll
        for (int i=0;i<4;i++)
            CPA(rb + (unsigned)(s*512 + (i*32+lane)*4)*4u, src + (i*32+lane)*4);
        CPC();
    }
    __syncthreads();   // s_cov ready
    #pragma unroll
    for (int tt=0; tt<8; tt++){
        if (tt < 5){
            const float* src = rowbase + (warp*8+tt+3)*D;
            int s = (tt+3)&3;
            #pragma unroll
            for (int i=0;i<4;i++)
                CPA(rb + (unsigned)(s*512 + (i*32+lane)*4)*4u, src + (i*32+lane)*4);
        }
        CPC();
        CPW3();
        float c = s_cov[warp*8+tt];
        const float4* xs = (const float4*)(wring + (tt&3)*512);
        float acc = 0.f;
        #pragma unroll
        for (int i=0;i<4;i++){
            float4 x = xs[i*32+lane];
            acc += ftanh(x.x + dec4[i].x + c*wc4[i].x)*v4[i].x;
            acc += ftanh(x.y + dec4[i].y + c*wc4[i].y)*v4[i].y;
            acc += ftanh(x.z + dec4[i].z + c*wc4[i].z)*v4[i].z;
            acc += ftanh(x.w + dec4[i].w + c*wc4[i].w)*v4[i].w;
        }
        acc = wsum(acc);
        if (!lane) s_scores[warp*8+tt] = acc;
    }
    __syncthreads();
    int sel = g_sel[b];
    if (warp == 0){
        float s0 = s_scores[lane], s1 = s_scores[lane+32];
        float m = wmax(fmaxf(s0,s1));
        float e0 = expf(s0-m), e1 = expf(s1-m);
        float den = wsum(e0+e1);
        float a0 = (e0/den)*tmask[ub*TK+lane];
        float a1 = (e1/den)*tmask[ub*TK+lane+32];
        float nf = wsum(a0+a1);
        float inv = 1.f/((nf==0.f)?1.f:nf);
        a0 *= inv; a1 *= inv;
        s_attn[lane] = a0; s_attn[lane+32] = a1;
        o_ntc[ub*TK+lane]    = s_cov[lane]    + a0;
        o_ntc[ub*TK+lane+32] = s_cov[lane+32] + a1;
        if (u == sel){ o_tattn[b*TK+lane] = a0; o_tattn[b*TK+lane+32] = a1; }
    }
    __syncthreads();
    if (u == sel){
        #pragma unroll
        for (int j=0;j<2;j++){
            int d = tid + j*256;
            float acc = 0.f;
            #pragma unroll 8
            for (int t=0;t<TK;t++) acc += s_attn[t]*tok[(long)ub*TK*D + t*D + d];
            g_target_out[b*D + d] = acc;
        }
    }
}

// ---------------- K5: h -> bf16 hi/lo (W1 rows in regs, 8 batches/block) -----
__global__ void k_h(const float* __restrict__ W1, const float* __restrict__ b1){
    int warp = threadIdx.x>>5, lane = threadIdx.x&31;
    int d = blockIdx.x*8 + warp;
    const float4* w = (const float4*)(W1 + (long)d*2*D);
    float4 w4[8];
    #pragma unroll
    for (int i=0;i<8;i++) w4[i] = w[i*32+lane];
    float bval = b1[d];
    #pragma unroll
    for (int bi=0; bi<8; bi++){
        int b = blockIdx.y*8 + bi;
        const float4* t0 = (const float4*)(g_target_out + b*D);
        const float4* t1 = (const float4*)(g_local_dec + b*D);
        float acc=0.f;
        #pragma unroll
        for (int i=0;i<4;i++){
            float4 x = t0[i*32+lane];
            acc += w4[i].x*x.x + w4[i].y*x.y + w4[i].z*x.z + w4[i].w*x.w;
        }
        #pragma unroll
        for (int i=0;i<4;i++){
            float4 x = t1[i*32+lane];
            acc += w4[i+4].x*x.x + w4[i+4].y*x.y + w4[i+4].z*x.z + w4[i+4].w*x.w;
        }
        acc = wsum(acc);
        if (!lane){
            float h = acc + bval;
            __nv_bfloat16 hi = __float2bfloat16(h);
            __nv_bfloat16 lo = __float2bfloat16(h - __bfloat162float(hi));
            ((__nv_bfloat16*)g_hhi)[b*512 + d] = hi;
            ((__nv_bfloat16*)g_hlo)[b*512 + d] = lo;
        }
    }
}

// ---------------- K6: vocab GEMM (per-warp cp.async pipelines, no mainloop sync)
#define BSTRIDE 268              // uint2 stride: word-stride 536 % 32 == 24 -> conflict-free
#define WROWP 24                 // floats per staged W row (conflict-free LDS.64)
#define WSTG (16*WROWP)          // floats per warp-stage = 384 (1536 B)
#define WNST 3                   // stages per warp
#define VOC_SMEM (8*WNST*WSTG*4 + 32*BSTRIDE*8)   // 36864 + 68608 = 105472 B
__global__ void __launch_bounds__(256)
k_vocab(const float* __restrict__ W2, const float* __restrict__ b2){
    extern __shared__ char smraw[];
    float* sW = (float*)smraw;                        // 8 warps x 3 stages x [16][24]
    uint2* sB = (uint2*)(smraw + 8*WNST*WSTG*4);      // 32 x 268
    __shared__ float sm_m[8][32], sm_s[8][32];
    int tid = threadIdx.x, wm = tid>>5, lane = tid&31;
    int g = lane>>2, tg = lane&3;
    long v0 = (long)blockIdx.x * 128;

    // stage B (plain stores; visible after the single __syncthreads below)
    for (int i = tid; i < 32*256; i += 256){
        int n = i >> 8, kp = i & 255;
        sB[n*BSTRIDE + kp] = make_uint2(g_hhi[i], g_hlo[i]);
    }

    // per-warp W staging geometry: warp wm owns rows [wm*16, wm*16+16)
    // each lane stages two 16B chunks per stage: idx = lane*2 + j
    int idx0 = lane*2, idx1 = lane*2+1;
    int row0 = idx0>>2, c40 = idx0&3;
    int row1 = idx1>>2, c41 = idx1&3;
    long gv0 = v0 + wm*16 + row0; if (gv0 >= V) gv0 = V-1;
    long gv1 = v0 + wm*16 + row1; if (gv1 >= V) gv1 = V-1;
    const float* src0 = W2 + gv0*D + c40*4;
    const float* src1 = W2 + gv1*D + c41*4;
    float* wbase = sW + wm*WNST*WSTG;
    unsigned sb = smem_u32(wbase);
    unsigned dst0 = sb + (unsigned)(row0*WROWP + c40*4)*4u;
    unsigned dst1 = sb + (unsigned)(row1*WROWP + c41*4)*4u;

    // prologue: chunks 0,1 -> stages 0,1 (per-warp groups 0,1)
    #pragma unroll
    for (int s=0; s<2; s++){
        CPA(dst0 + (unsigned)(s*WSTG)*4u, src0 + s*16);
        CPA(dst1 + (unsigned)(s*WSTG)*4u, src1 + s*16);
        CPC();
    }
    __syncthreads();   // sB visible; only sync before the mainloop

    float dd[4][4];
    #pragma unroll
    for (int nt=0;nt<4;nt++){ dd[nt][0]=dd[nt][1]=dd[nt][2]=dd[nt][3]=0.f; }

    for (int kc=0; kc<32; kc++){
        CPW1();   // per-warp groups 0..kc complete -> chunk kc resident
        if (kc+2 < 32){
            unsigned st = (unsigned)((kc+2)%WNST)*WSTG*4u;
            CPA(dst0 + st, src0 + (kc+2)*16);
            CPA(dst1 + st, src1 + (kc+2)*16);
        }
        CPC();    // unconditional: exactly one group per iteration

        const float* sw = wbase + (kc%WNST)*WSTG;
        float2 fa0 = *(const float2*)(sw + g*WROWP + tg*2);
        float2 fa1 = *(const float2*)(sw + (g+8)*WROWP + tg*2);
        float2 fa2 = *(const float2*)(sw + g*WROWP + tg*2 + 8);
        float2 fa3 = *(const float2*)(sw + (g+8)*WROWP + tg*2 + 8);

        unsigned ah0,al0,ah1,al1,ah2,al2,ah3,al3;
        cvt_hilo(fa0, ah0, al0);
        cvt_hilo(fa1, ah1, al1);
        cvt_hilo(fa2, ah2, al2);
        cvt_hilo(fa3, ah3, al3);

        int kp = kc*8 + tg;
        #pragma unroll
        for (int nt=0; nt<4; nt++){
            int nrow = (nt*8 + g)*BSTRIDE;
            uint2 b0 = sB[nrow + kp];
            uint2 b1 = sB[nrow + kp + 4];
            mma16816(dd[nt], ah0, ah1, ah2, ah3, b0.x, b1.x);  // hi*hi
            mma16816(dd[nt], al0, al1, al2, al3, b0.x, b1.x);  // lo*hi
            mma16816(dd[nt], ah0, ah1, ah2, ah3, b0.y, b1.y);  // hi*lo
        }
    }

    long rr0 = v0 + wm*16 + g;
    long rr1 = rr0 + 8;
    bool ok0 = (rr0 < V), ok1 = (rr1 < V);
    float bias0 = ok0 ? b2[rr0] : 0.f;
    float bias1 = ok1 ? b2[rr1] : 0.f;
    #pragma unroll
    for (int nt=0; nt<4; nt++){
        int n = nt*8 + tg*2;
        if (ok0){
            g_logits[(long)n*V + rr0]     = dd[nt][0] + bias0;
            g_logits[(long)(n+1)*V + rr0] = dd[nt][1] + bias0;
        }
        if (ok1){
            g_logits[(long)n*V + rr1]     = dd[nt][2] + bias1;
            g_logits[(long)(n+1)*V + rr1] = dd[nt][3] + bias1;
        }
    }

    // ---- fused partial softmax stats: per (block, n) (max, sumexp) ----
    #pragma unroll
    for (int nt=0; nt<4; nt++){
        #pragma unroll
        for (int p=0; p<2; p++){
            float x0 = ok0 ? dd[nt][p]   + bias0 : -1e30f;
            float x1 = ok1 ? dd[nt][p+2] + bias1 : -1e30f;
            float m = fmaxf(x0, x1);
            #pragma unroll
            for (int o=4; o<32; o<<=1) m = fmaxf(m, __shfl_xor_sync(0xffffffffu, m, o));
            float s = (ok0 ? expf(x0 - m) : 0.f) + (ok1 ? expf(x1 - m) : 0.f);
            #pragma unroll
            for (int o=4; o<32; o<<=1) s += __shfl_xor_sync(0xffffffffu, s, o);
            if (g == 0){
                int n = nt*8 + tg*2 + p;
                sm_m[wm][n] = m;
                sm_s[wm][n] = s;
            }
        }
    }
    __syncthreads();
    if (wm == 0){
        float M = -1e30f;
        #pragma unroll
        for (int w=0; w<8; w++) M = fmaxf(M, sm_m[w][lane]);
        float S = 0.f;
        #pragma unroll
        for (int w=0; w<8; w++) S += sm_s[w][lane] * expf(sm_m[w][lane] - M);
        g_pm[(long)lane*512 + blockIdx.x] = M;
        g_ps[(long)lane*512 + blockIdx.x] = S;
    }
}

// ---------------- K7: combine partial stats (tiny) ----------------
__global__ void k_red(){
    int b = blockIdx.x, tid = threadIdx.x;
    __shared__ float smm[256], sms[256];
    float m0 = (tid      < NVBLK) ? g_pm[(long)b*512 + tid]       : -1e30f;
    float s0 = (tid      < NVBLK) ? g_ps[(long)b*512 + tid]       : 0.f;
    float m1 = (tid+256  < NVBLK) ? g_pm[(long)b*512 + tid + 256] : -1e30f;
    float s1 = (tid+256  < NVBLK) ? g_ps[(long)b*512 + tid + 256] : 0.f;
    float m = fmaxf(m0, m1);
    smm[tid] = m;
    __syncthreads();
    for (int o=128;o;o>>=1){ if (tid<o) smm[tid]=fmaxf(smm[tid],smm[tid+o]); __syncthreads(); }
    float M = smm[0];
    __syncthreads();
    float s = s0*expf(m0 - M) + s1*expf(m1 - M);
    sms[tid] = s;
    __syncthreads();
    for (int o=128;o;o>>=1){ if (tid<o) sms[tid]+=sms[tid+o]; __syncthreads(); }
    if (!tid){ g_m[b] = M; g_inv_s[b] = 1.f/sms[0]; }
}

// ---------------- K8: vocab_dist ----------------
__global__ void k_soft(float* __restrict__ o_vocab){
    long i = (long)blockIdx.x*256 + threadIdx.x;
    if (i >= (long)B*V) return;
    int b = (int)(i / V);
    o_vocab[i] = expf(g_logits[i] - g_m[b]) * g_inv_s[b];
}

// ---------------- launch ----------------
extern "C" void kernel_launch(void* const* d_in, const int* in_sizes, int n_in,
                              void* d_out, int out_size){
    const float* tf    = (const float*)d_in[0];
    const float* enc   = (const float*)d_in[2];
    const float* umask = (const float*)d_in[3];
    const float* tok   = (const float*)d_in[4];
    const float* tmask = (const float*)d_in[5];
    const float* cov   = (const float*)d_in[6];
    const float* tcov  = (const float*)d_in[7];
    const float* ua_Wp = (const float*)d_in[8];
    const float* ua_bp = (const float*)d_in[9];
    const float* ua_v  = (const float*)d_in[10];
    const float* ua_wc = (const float*)d_in[11];
    const float* ta_Wp = (const float*)d_in[12];
    const float* ta_bp = (const float*)d_in[13];
    const float* ta_v  = (const float*)d_in[14];
    const float* ta_wc = (const float*)d_in[15];
    const float* pgen_W= (const float*)d_in[16];
    const float* pgen_b= (const float*)d_in[17];
    const float* W1    = (const float*)d_in[18];
    const float* b1    = (const float*)d_in[19];
    const float* W2    = (const float*)d_in[20];
    const float* b2    = (const float*)d_in[21];
    const float* ln_g  = (const float*)d_in[22];
    const float* ln_b  = (const float*)d_in[23];

    float* out = (float*)d_out;
    float* o_vocab = out;
    float* o_tattn = o_vocab + (long)B*V;
    float* o_pgen  = o_tattn + B*TK;
    float* o_ucov  = o_pgen + B;
    float* o_ntc   = o_ucov + B*U;
    float* o_uidx  = o_ntc + (long)U*B*TK;

    cudaFuncSetAttribute(k_tatt, cudaFuncAttributeMaxDynamicSharedMemorySize, 65536);
    cudaFuncSetAttribute(k_vocab, cudaFuncAttributeMaxDynamicSharedMemorySize, VOC_SMEM);

    k_ln   <<<B, 256>>>(tf, ln_g, ln_b);
    k_proj <<<dim3(D/8, B/8, 2), 256>>>(ua_Wp, ua_bp, ta_Wp, ta_bp);
    k_uatt <<<B, 256>>>(enc, umask, cov, ua_wc, ua_v, pgen_W, pgen_b,
                        o_ucov, o_pgen, o_uidx);
    k_tatt <<<dim3(U, B), 256, 65536>>>(tok, tmask, tcov, ta_wc, ta_v, o_ntc, o_tattn);
    k_h    <<<dim3(D/8, B/8), 256>>>(W1, b1);
    k_vocab<<<NVBLK, 256, VOC_SMEM>>>(W2, b2);
    k_red  <<<B, 256>>>();
    k_soft <<<(int)(((long)B*V + 255)/256), 256>>>(o_vocab);
}

// round 12
// speedup vs baseline: 1.1685x; 1.0768x over previous
#include <cuda_runtime.h>
#include <cuda_bf16.h>

#define B   32
#define U   32
#define TK  64
#define TDEC 64
#define D   512
#define V   50257
#define NVBLK 393     // (V+127)/128

// ---------------- scratch ----------------
__device__ float g_local_dec[B*D];
__device__ float g_dec_ua[B*D];
__device__ float g_dec_ta[B*D];
__device__ float g_target_out[B*D];
__device__ int   g_sel[B];
__device__ float g_logits[(long)B*V];
__device__ float g_m[B];
__device__ float g_inv_s[B];
__device__ unsigned g_hhi[B*256];   // [b][kpair] bf16x2 of h_hi
__device__ unsigned g_hlo[B*256];   // [b][kpair] bf16x2 of h_lo
__device__ float g_pm[B*512];       // per-(b, vblock) partial max
__device__ float g_ps[B*512];       // per-(b, vblock) partial sumexp

// ---------------- helpers ----------------
__device__ __forceinline__ float ftanh(float x){
    float y; asm("tanh.approx.f32 %0, %1;" : "=f"(y) : "f"(x)); return y;
}
__device__ __forceinline__ float wsum(float v){
    #pragma unroll
    for (int o=16;o;o>>=1) v += __shfl_xor_sync(0xffffffffu, v, o);
    return v;
}
__device__ __forceinline__ float wmax(float v){
    #pragma unroll
    for (int o=16;o;o>>=1) v = fmaxf(v, __shfl_xor_sync(0xffffffffu, v, o));
    return v;
}
__device__ __forceinline__ unsigned smem_u32(const void* p){
    unsigned a;
    asm("{ .reg .u64 t; cvta.to.shared.u64 t, %1; cvt.u32.u64 %0, t; }" : "=r"(a) : "l"(p));
    return a;
}

// cp.async
#define CPA(dst, src) asm volatile("cp.async.cg.shared.global [%0], [%1], 16;" :: "r"(dst), "l"(src) : "memory")
#define CPC()  asm volatile("cp.async.commit_group;" ::: "memory")
#define CPW3() asm volatile("cp.async.wait_group 3;" ::: "memory")

// bf16 mma m16n8k16
__device__ __forceinline__ void mma16816(float* d, unsigned a0, unsigned a1,
                                         unsigned a2, unsigned a3,
                                         unsigned b0, unsigned b1){
    asm volatile("mma.sync.aligned.m16n8k16.row.col.f32.bf16.bf16.f32 "
        "{%0,%1,%2,%3}, {%4,%5,%6,%7}, {%8,%9}, {%0,%1,%2,%3};"
        : "+f"(d[0]), "+f"(d[1]), "+f"(d[2]), "+f"(d[3])
        : "r"(a0), "r"(a1), "r"(a2), "r"(a3), "r"(b0), "r"(b1));
}
__device__ __forceinline__ void cvt_hilo(float2 f, unsigned &hi, unsigned &lo){
    __nv_bfloat162 h = __float22bfloat162_rn(f);
    float2 fh = __bfloat1622float2(h);
    __nv_bfloat162 l = __float22bfloat162_rn(make_float2(f.x - fh.x, f.y - fh.y));
    hi = *(unsigned*)&h; lo = *(unsigned*)&l;
}

// ---------------- K1: layernorm ----------------
__global__ void k_ln(const float* __restrict__ tf, const float* __restrict__ g,
                     const float* __restrict__ bb){
    int b = blockIdx.x, tid = threadIdx.x;
    const float* row = tf + (b*TDEC + (TDEC-1))*D;
    float x0 = row[tid], x1 = row[tid+256];
    __shared__ float s1[256], s2[256];
    s1[tid] = x0+x1; s2[tid] = x0*x0 + x1*x1;
    __syncthreads();
    for (int o=128;o;o>>=1){
        if (tid<o){ s1[tid]+=s1[tid+o]; s2[tid]+=s2[tid+o]; }
        __syncthreads();
    }
    float mu = s1[0]*(1.0f/D);
    float var = s2[0]*(1.0f/D) - mu*mu;
    float r = rsqrtf(var + 1e-5f);
    g_local_dec[b*D+tid]     = (x0-mu)*r*g[tid]     + bb[tid];
    g_local_dec[b*D+tid+256] = (x1-mu)*r*g[tid+256] + bb[tid+256];
}

// ---------------- K2: dec projections (W rows in regs, 8 batches/block) ------
__global__ void k_proj(const float* __restrict__ ua_Wp, const float* __restrict__ ua_bp,
                       const float* __restrict__ ta_Wp, const float* __restrict__ ta_bp){
    int which = blockIdx.z;
    const float* W    = which ? ta_Wp : ua_Wp;
    const float* bias = which ? ta_bp : ua_bp;
    float* outp       = which ? g_dec_ta : g_dec_ua;
    int warp = threadIdx.x >> 5, lane = threadIdx.x & 31;
    int d = blockIdx.x*8 + warp;
    const float4* wrow = (const float4*)(W + (long)d*D);
    float4 w4[4];
    #pragma unroll
    for (int i=0;i<4;i++) w4[i] = wrow[i*32 + lane];
    float bval = bias[d];
    #pragma unroll
    for (int bi=0; bi<8; bi++){
        int b = blockIdx.y*8 + bi;
        const float4* t = (const float4*)(g_local_dec + b*D);
        float acc = 0.f;
        #pragma unroll
        for (int i=0;i<4;i++){
            float4 t4 = t[i*32 + lane];
            acc += w4[i].x*t4.x + w4[i].y*t4.y + w4[i].z*t4.z + w4[i].w*t4.w;
        }
        acc = wsum(acc);
        if (!lane) outp[b*D + d] = acc + bval;
    }
}

// ---------------- K3: utterance attention + argmax + p_gen ----------------
__global__ void k_uatt(const float* __restrict__ enc, const float* __restrict__ umask,
                       const float* __restrict__ cov, const float* __restrict__ ua_wc,
                       const float* __restrict__ ua_v, const float* __restrict__ pgen_W,
                       const float* __restrict__ pgen_b,
                       float* __restrict__ o_ucov, float* __restrict__ o_pgen,
                       float* __restrict__ o_uidx){
    int b = blockIdx.x, tid = threadIdx.x;
    int warp = tid>>5, lane = tid&31;
    __shared__ float s_scores[U], s_attn[U], s_red[256];
    float4 dec4[4], wc4[4], v4[4];
    #pragma unroll
    for (int i=0;i<4;i++){
        int d = i*128 + lane*4;
        dec4[i] = *(const float4*)(g_dec_ua + b*D + d);
        wc4[i]  = *(const float4*)(ua_wc + d);
        v4[i]   = *(const float4*)(ua_v + d);
    }
    #pragma unroll
    for (int uu=0; uu<4; uu++){
        int u = warp + uu*8;
        float c = cov[b*U + u];
        const float4* e = (const float4*)(enc + (long)(b*U + u)*D);
        float acc = 0.f;
        #pragma unroll
        for (int i=0;i<4;i++){
            float4 x = e[i*32 + lane];
            acc += ftanh(x.x + dec4[i].x + c*wc4[i].x) * v4[i].x;
            acc += ftanh(x.y + dec4[i].y + c*wc4[i].y) * v4[i].y;
            acc += ftanh(x.z + dec4[i].z + c*wc4[i].z) * v4[i].z;
            acc += ftanh(x.w + dec4[i].w + c*wc4[i].w) * v4[i].w;
        }
        acc = wsum(acc);
        if (!lane) s_scores[u] = acc;
    }
    __syncthreads();
    if (warp == 0){
        int u = lane;
        float s = s_scores[u];
        float m = wmax(s);
        float e = expf(s - m);
        float den = wsum(e);
        float a_ = (e/den) * umask[b*U+u];
        float nf = wsum(a_);
        float attn = a_ / (nf == 0.f ? 1.f : nf);
        s_attn[u] = attn;
        o_ucov[b*U+u] = cov[b*U+u] + attn;
        float bv = attn; int bi = u;
        #pragma unroll
        for (int o=16;o;o>>=1){
            float ov = __shfl_xor_sync(0xffffffffu, bv, o);
            int   oi = __shfl_xor_sync(0xffffffffu, bi, o);
            if (ov > bv || (ov == bv && oi < bi)){ bv = ov; bi = oi; }
        }
        if (!lane){ g_sel[b] = bi; o_uidx[b] = (float)bi; }
    }
    __syncthreads();
    float part = 0.f;
    #pragma unroll
    for (int j=0;j<2;j++){
        int d = tid + j*256;
        float acc = 0.f;
        #pragma unroll 8
        for (int u=0;u<U;u++) acc += s_attn[u] * enc[(long)(b*U+u)*D + d];
        part += pgen_W[d]*acc + pgen_W[D + d]*g_local_dec[b*D + d];
    }
    s_red[tid] = part;
    __syncthreads();
    for (int o=128;o;o>>=1){ if (tid<o) s_red[tid]+=s_red[tid+o]; __syncthreads(); }
    if (!tid) o_pgen[b] = 1.f/(1.f + expf(-(s_red[0] + pgen_b[0])));
}

// ---------------- K4: token attention (R5 exact: 4-stage ring, wait_group 3) --
__global__ void __launch_bounds__(256,3)
k_tatt(const float* __restrict__ tok, const float* __restrict__ tmask,
       const float* __restrict__ tcov, const float* __restrict__ ta_wc,
       const float* __restrict__ ta_v,
       float* __restrict__ o_ntc, float* __restrict__ o_tattn){
    extern __shared__ float ring[];   // 8 warps * 4 stages * 512 floats = 64KB
    __shared__ float s_scores[TK], s_attn[TK], s_cov[TK];
    int u = blockIdx.x, b = blockIdx.y;
    int tid = threadIdx.x, warp = tid>>5, lane = tid&31;
    int ub = u*B + b;
    float* wring = ring + warp*2048;
    unsigned rb = smem_u32(wring);
    const float* rowbase = tok + (long)ub*TK*D;
    if (tid < TK) s_cov[tid] = tcov[ub*TK + tid];

    float4 dec4[4], wc4[4], v4[4];
    #pragma unroll
    for (int i=0;i<4;i++){
        int d = i*128 + lane*4;
        dec4[i] = *(const float4*)(g_dec_ta + b*D + d);
        wc4[i]  = *(const float4*)(ta_wc + d);
        v4[i]   = *(const float4*)(ta_v + d);
    }
    #pragma unroll
    for (int s=0;s<3;s++){
        const float* src = rowbase + (warp*8+s)*D;
        #pragma unroll
        for (int i=0;i<4;i++)
            CPA(rb + (unsigned)(s*512 + (i*32+lane)*4)*4u, src + (i*32+lane)*4);
        CPC();
    }
    __syncthreads();   // s_cov ready
    #pragma unroll
    for (int tt=0; tt<8; tt++){
        if (tt < 5){
            const float* src = rowbase + (warp*8+tt+3)*D;
            int s = (tt+3)&3;
            #pragma unroll
            for (int i=0;i<4;i++)
                CPA(rb + (unsigned)(s*512 + (i*32+lane)*4)*4u, src + (i*32+lane)*4);
        }
        CPC();
        CPW3();
        float c = s_cov[warp*8+tt];
        const float4* xs = (const float4*)(wring + (tt&3)*512);
        float acc = 0.f;
        #pragma unroll
        for (int i=0;i<4;i++){
            float4 x = xs[i*32+lane];
            acc += ftanh(x.x + dec4[i].x + c*wc4[i].x)*v4[i].x;
            acc += ftanh(x.y + dec4[i].y + c*wc4[i].y)*v4[i].y;
            acc += ftanh(x.z + dec4[i].z + c*wc4[i].z)*v4[i].z;
            acc += ftanh(x.w + dec4[i].w + c*wc4[i].w)*v4[i].w;
        }
        acc = wsum(acc);
        if (!lane) s_scores[warp*8+tt] = acc;
    }
    __syncthreads();
    int sel = g_sel[b];
    if (warp == 0){
        float s0 = s_scores[lane], s1 = s_scores[lane+32];
        float m = wmax(fmaxf(s0,s1));
        float e0 = expf(s0-m), e1 = expf(s1-m);
        float den = wsum(e0+e1);
        float a0 = (e0/den)*tmask[ub*TK+lane];
        float a1 = (e1/den)*tmask[ub*TK+lane+32];
        float nf = wsum(a0+a1);
        float inv = 1.f/((nf==0.f)?1.f:nf);
        a0 *= inv; a1 *= inv;
        s_attn[lane] = a0; s_attn[lane+32] = a1;
        o_ntc[ub*TK+lane]    = s_cov[lane]    + a0;
        o_ntc[ub*TK+lane+32] = s_cov[lane+32] + a1;
        if (u == sel){ o_tattn[b*TK+lane] = a0; o_tattn[b*TK+lane+32] = a1; }
    }
    __syncthreads();
    if (u == sel){
        #pragma unroll
        for (int j=0;j<2;j++){
            int d = tid + j*256;
            float acc = 0.f;
            #pragma unroll 8
            for (int t=0;t<TK;t++) acc += s_attn[t]*tok[(long)ub*TK*D + t*D + d];
            g_target_out[b*D + d] = acc;
        }
    }
}

// ---------------- K5: h -> bf16 hi/lo (W1 rows in regs, 8 batches/block) -----
__global__ void k_h(const float* __restrict__ W1, const float* __restrict__ b1){
    int warp = threadIdx.x>>5, lane = threadIdx.x&31;
    int d = blockIdx.x*8 + warp;
    const float4* w = (const float4*)(W1 + (long)d*2*D);
    float4 w4[8];
    #pragma unroll
    for (int i=0;i<8;i++) w4[i] = w[i*32+lane];
    float bval = b1[d];
    #pragma unroll
    for (int bi=0; bi<8; bi++){
        int b = blockIdx.y*8 + bi;
        const float4* t0 = (const float4*)(g_target_out + b*D);
        const float4* t1 = (const float4*)(g_local_dec + b*D);
        float acc=0.f;
        #pragma unroll
        for (int i=0;i<4;i++){
            float4 x = t0[i*32+lane];
            acc += w4[i].x*x.x + w4[i].y*x.y + w4[i].z*x.z + w4[i].w*x.w;
        }
        #pragma unroll
        for (int i=0;i<4;i++){
            float4 x = t1[i*32+lane];
            acc += w4[i+4].x*x.x + w4[i+4].y*x.y + w4[i+4].z*x.z + w4[i+4].w*x.w;
        }
        acc = wsum(acc);
        if (!lane){
            float h = acc + bval;
            __nv_bfloat16 hi = __float2bfloat16(h);
            __nv_bfloat16 lo = __float2bfloat16(h - __bfloat162float(hi));
            ((__nv_bfloat16*)g_hhi)[b*512 + d] = hi;
            ((__nv_bfloat16*)g_hlo)[b*512 + d] = lo;
        }
    }
}

// ---------------- K6: vocab GEMM (per-warp 5-stage cp.async, swizzled W) -----
#define BSTRIDE 260              // uint2 stride: phase-split conflict-free
#define WNST 5                   // stages per warp
#define WSTGF 256                // floats per stage (16 rows x 16 floats, swizzled)
#define VOC_SMEM (8*WNST*WSTGF*4 + 32*BSTRIDE*8)   // 40960 + 66560 = 107520 B
__global__ void __launch_bounds__(256)
k_vocab(const float* __restrict__ W2, const float* __restrict__ b2){
    extern __shared__ char smraw[];
    float* sW = (float*)smraw;                        // 8 warps x 5 stages x 1KB
    uint2* sB = (uint2*)(smraw + 8*WNST*WSTGF*4);     // 32 x 260
    __shared__ float sm_m[8][32], sm_s[8][32];
    int tid = threadIdx.x, wm = tid>>5, lane = tid&31;
    int g = lane>>2, tg = lane&3;
    long v0 = (long)blockIdx.x * 128;

    // stage B (plain stores; visible after the single __syncthreads below)
    for (int i = tid; i < 32*256; i += 256){
        int n = i >> 8, kp = i & 255;
        sB[n*BSTRIDE + kp] = make_uint2(g_hhi[i], g_hlo[i]);
    }

    // per-warp W staging: warp wm owns rows [wm*16, +16); lane stages 2 x 16B chunks
    // swizzled layout within a 1KB stage: phys_chunk = c4 ^ (row & 3)
    int idx0 = lane*2, idx1 = lane*2+1;
    int row0 = idx0>>2, c40 = idx0&3;
    int row1 = idx1>>2, c41 = idx1&3;
    long gv0 = v0 + wm*16 + row0; if (gv0 >= V) gv0 = V-1;
    long gv1 = v0 + wm*16 + row1; if (gv1 >= V) gv1 = V-1;
    const float* src0 = W2 + gv0*D + c40*4;
    const float* src1 = W2 + gv1*D + c41*4;
    float* wbase = sW + wm*WNST*WSTGF;
    unsigned sb = smem_u32(wbase);
    unsigned dst0 = sb + (unsigned)(row0*64 + ((c40 ^ (row0&3))*16));
    unsigned dst1 = sb + (unsigned)(row1*64 + ((c41 ^ (row1&3))*16));

    // prologue: chunks 0..3 -> stages 0..3 (per-warp groups 0..3)
    #pragma unroll
    for (int s=0; s<4; s++){
        CPA(dst0 + (unsigned)s*1024u, src0 + s*16);
        CPA(dst1 + (unsigned)s*1024u, src1 + s*16);
        CPC();
    }
    __syncthreads();   // sB visible; only block-wide sync before the mainloop

    float dd[4][4];
    #pragma unroll
    for (int nt=0;nt<4;nt++){ dd[nt][0]=dd[nt][1]=dd[nt][2]=dd[nt][3]=0.f; }

    // fragment read offsets within a (swizzled) stage
    int r3 = g & 3;
    int o_lo = ((tg>>1) ^ r3)*4 + (tg&1)*2;         // cols tg*2   (chunk tg>>1)
    int o_hi = (((tg>>1)|2) ^ r3)*4 + (tg&1)*2;     // cols tg*2+8 (chunk 2+(tg>>1))
    int rA = g*16, rB = (g+8)*16;

    for (int kc=0; kc<32; kc++){
        CPW3();   // per-warp groups 0..kc complete -> chunk kc resident
        if (kc+4 < 32){
            unsigned st = (unsigned)((kc+4)%WNST)*1024u;
            CPA(dst0 + st, src0 + (kc+4)*16);
            CPA(dst1 + st, src1 + (kc+4)*16);
        }
        CPC();    // unconditional: exactly one group per iteration

        const float* sw = wbase + (kc%WNST)*WSTGF;
        float2 fa0 = *(const float2*)(sw + rA + o_lo);
        float2 fa1 = *(const float2*)(sw + rB + o_lo);
        float2 fa2 = *(const float2*)(sw + rA + o_hi);
        float2 fa3 = *(const float2*)(sw + rB + o_hi);

        unsigned ah0,al0,ah1,al1,ah2,al2,ah3,al3;
        cvt_hilo(fa0, ah0, al0);
        cvt_hilo(fa1, ah1, al1);
        cvt_hilo(fa2, ah2, al2);
        cvt_hilo(fa3, ah3, al3);

        int kp = kc*8 + tg;
        #pragma unroll
        for (int nt=0; nt<4; nt++){
            int nrow = (nt*8 + g)*BSTRIDE;
            uint2 b0 = sB[nrow + kp];
            uint2 b1 = sB[nrow + kp + 4];
            mma16816(dd[nt], ah0, ah1, ah2, ah3, b0.x, b1.x);  // hi*hi
            mma16816(dd[nt], al0, al1, al2, al3, b0.x, b1.x);  // lo*hi
            mma16816(dd[nt], ah0, ah1, ah2, ah3, b0.y, b1.y);  // hi*lo
        }
    }

    long rr0 = v0 + wm*16 + g;
    long rr1 = rr0 + 8;
    bool ok0 = (rr0 < V), ok1 = (rr1 < V);
    float bias0 = ok0 ? b2[rr0] : 0.f;
    float bias1 = ok1 ? b2[rr1] : 0.f;
    #pragma unroll
    for (int nt=0; nt<4; nt++){
        int n = nt*8 + tg*2;
        if (ok0){
            g_logits[(long)n*V + rr0]     = dd[nt][0] + bias0;
            g_logits[(long)(n+1)*V + rr0] = dd[nt][1] + bias0;
        }
        if (ok1){
            g_logits[(long)n*V + rr1]     = dd[nt][2] + bias1;
            g_logits[(long)(n+1)*V + rr1] = dd[nt][3] + bias1;
        }
    }

    // ---- fused partial softmax stats: per (block, n) (max, sumexp) ----
    #pragma unroll
    for (int nt=0; nt<4; nt++){
        #pragma unroll
        for (int p=0; p<2; p++){
            float x0 = ok0 ? dd[nt][p]   + bias0 : -1e30f;
            float x1 = ok1 ? dd[nt][p+2] + bias1 : -1e30f;
            float m = fmaxf(x0, x1);
            #pragma unroll
            for (int o=4; o<32; o<<=1) m = fmaxf(m, __shfl_xor_sync(0xffffffffu, m, o));
            float s = (ok0 ? expf(x0 - m) : 0.f) + (ok1 ? expf(x1 - m) : 0.f);
            #pragma unroll
            for (int o=4; o<32; o<<=1) s += __shfl_xor_sync(0xffffffffu, s, o);
            if (g == 0){
                int n = nt*8 + tg*2 + p;
                sm_m[wm][n] = m;
                sm_s[wm][n] = s;
            }
        }
    }
    __syncthreads();
    if (wm == 0){
        float M = -1e30f;
        #pragma unroll
        for (int w=0; w<8; w++) M = fmaxf(M, sm_m[w][lane]);
        float S = 0.f;
        #pragma unroll
        for (int w=0; w<8; w++) S += sm_s[w][lane] * expf(sm_m[w][lane] - M);
        g_pm[(long)lane*512 + blockIdx.x] = M;
        g_ps[(long)lane*512 + blockIdx.x] = S;
    }
}

// ---------------- K7: combine partial stats (tiny) ----------------
__global__ void k_red(){
    int b = blockIdx.x, tid = threadIdx.x;
    __shared__ float smm[256], sms[256];
    float m0 = (tid      < NVBLK) ? g_pm[(long)b*512 + tid]       : -1e30f;
    float s0 = (tid      < NVBLK) ? g_ps[(long)b*512 + tid]       : 0.f;
    float m1 = (tid+256  < NVBLK) ? g_pm[(long)b*512 + tid + 256] : -1e30f;
    float s1 = (tid+256  < NVBLK) ? g_ps[(long)b*512 + tid + 256] : 0.f;
    float m = fmaxf(m0, m1);
    smm[tid] = m;
    __syncthreads();
    for (int o=128;o;o>>=1){ if (tid<o) smm[tid]=fmaxf(smm[tid],smm[tid+o]); __syncthreads(); }
    float M = smm[0];
    __syncthreads();
    float s = s0*expf(m0 - M) + s1*expf(m1 - M);
    sms[tid] = s;
    __syncthreads();
    for (int o=128;o;o>>=1){ if (tid<o) sms[tid]+=sms[tid+o]; __syncthreads(); }
    if (!tid){ g_m[b] = M; g_inv_s[b] = 1.f/sms[0]; }
}

// ---------------- K8: vocab_dist ----------------
__global__ void k_soft(float* __restrict__ o_vocab){
    long i = (long)blockIdx.x*256 + threadIdx.x;
    if (i >= (long)B*V) return;
    int b = (int)(i / V);
    o_vocab[i] = expf(g_logits[i] - g_m[b]) * g_inv_s[b];
}

// ---------------- launch ----------------
extern "C" void kernel_launch(void* const* d_in, const int* in_sizes, int n_in,
                              void* d_out, int out_size){
    const float* tf    = (const float*)d_in[0];
    const float* enc   = (const float*)d_in[2];
    const float* umask = (const float*)d_in[3];
    const float* tok   = (const float*)d_in[4];
    const float* tmask = (const float*)d_in[5];
    const float* cov   = (const float*)d_in[6];
    const float* tcov  = (const float*)d_in[7];
    const float* ua_Wp = (const float*)d_in[8];
    const float* ua_bp = (const float*)d_in[9];
    const float* ua_v  = (const float*)d_in[10];
    const float* ua_wc = (const float*)d_in[11];
    const float* ta_Wp = (const float*)d_in[12];
    const float* ta_bp = (const float*)d_in[13];
    const float* ta_v  = (const float*)d_in[14];
    const float* ta_wc = (const float*)d_in[15];
    const float* pgen_W= (const float*)d_in[16];
    const float* pgen_b= (const float*)d_in[17];
    const float* W1    = (const float*)d_in[18];
    const float* b1    = (const float*)d_in[19];
    const float* W2    = (const float*)d_in[20];
    const float* b2    = (const float*)d_in[21];
    const float* ln_g  = (const float*)d_in[22];
    const float* ln_b  = (const float*)d_in[23];

    float* out = (float*)d_out;
    float* o_vocab = out;
    float* o_tattn = o_vocab + (long)B*V;
    float* o_pgen  = o_tattn + B*TK;
    float* o_ucov  = o_pgen + B;
    float* o_ntc   = o_ucov + B*U;
    float* o_uidx  = o_ntc + (long)U*B*TK;

    cudaFuncSetAttribute(k_tatt, cudaFuncAttributeMaxDynamicSharedMemorySize, 65536);
    cudaFuncSetAttribute(k_vocab, cudaFuncAttributeMaxDynamicSharedMemorySize, VOC_SMEM);

    k_ln   <<<B, 256>>>(tf, ln_g, ln_b);
    k_proj <<<dim3(D/8, B/8, 2), 256>>>(ua_Wp, ua_bp, ta_Wp, ta_bp);
    k_uatt <<<B, 256>>>(enc, umask, cov, ua_wc, ua_v, pgen_W, pgen_b,
                        o_ucov, o_pgen, o_uidx);
    k_tatt <<<dim3(U, B), 256, 65536>>>(tok, tmask, tcov, ta_wc, ta_v, o_ntc, o_tattn);
    k_h    <<<dim3(D/8, B/8), 256>>>(W1, b1);
    k_vocab<<<NVBLK, 256, VOC_SMEM>>>(W2, b2);
    k_red  <<<B, 256>>>();
    k_soft <<<(int)(((long)B*V + 255)/256), 256>>>(o_vocab);
}

// round 13
// speedup vs baseline: 1.1720x; 1.0030x over previous
#include <cuda_runtime.h>
#include <cuda_bf16.h>

#define B   32
#define U   32
#define TK  64
#define TDEC 64
#define D   512
#define V   50257
#define NVBLK 393     // (V+127)/128

// ---------------- scratch ----------------
__device__ float g_local_dec[B*D];
__device__ float g_dec_ua[B*D];
__device__ float g_dec_ta[B*D];
__device__ float g_target_out[B*D];
__device__ int   g_sel[B];
__device__ float g_logits[(long)B*V];
__device__ float g_m[B];
__device__ float g_inv_s[B];
__device__ unsigned g_hhi[B*256];   // [b][kpair] bf16x2 of h_hi
__device__ unsigned g_hlo[B*256];   // [b][kpair] bf16x2 of h_lo
__device__ uint4 g_hp[B*128];       // [b][kc*4+tg] = {hi[kp], lo[kp], hi[kp+4], lo[kp+4]}
__device__ float g_pm[B*512];       // per-(b, vblock) partial max
__device__ float g_ps[B*512];       // per-(b, vblock) partial sumexp

// ---------------- helpers ----------------
__device__ __forceinline__ float ftanh(float x){
    float y; asm("tanh.approx.f32 %0, %1;" : "=f"(y) : "f"(x)); return y;
}
__device__ __forceinline__ float wsum(float v){
    #pragma unroll
    for (int o=16;o;o>>=1) v += __shfl_xor_sync(0xffffffffu, v, o);
    return v;
}
__device__ __forceinline__ float wmax(float v){
    #pragma unroll
    for (int o=16;o;o>>=1) v = fmaxf(v, __shfl_xor_sync(0xffffffffu, v, o));
    return v;
}
__device__ __forceinline__ unsigned smem_u32(const void* p){
    unsigned a;
    asm("{ .reg .u64 t; cvta.to.shared.u64 t, %1; cvt.u32.u64 %0, t; }" : "=r"(a) : "l"(p));
    return a;
}

// cp.async
#define CPA(dst, src) asm volatile("cp.async.cg.shared.global [%0], [%1], 16;" :: "r"(dst), "l"(src) : "memory")
#define CPC()  asm volatile("cp.async.commit_group;" ::: "memory")
#define CPW3() asm volatile("cp.async.wait_group 3;" ::: "memory")

// bf16 mma m16n8k16
__device__ __forceinline__ void mma16816(float* d, unsigned a0, unsigned a1,
                                         unsigned a2, unsigned a3,
                                         unsigned b0, unsigned b1){
    asm volatile("mma.sync.aligned.m16n8k16.row.col.f32.bf16.bf16.f32 "
        "{%0,%1,%2,%3}, {%4,%5,%6,%7}, {%8,%9}, {%0,%1,%2,%3};"
        : "+f"(d[0]), "+f"(d[1]), "+f"(d[2]), "+f"(d[3])
        : "r"(a0), "r"(a1), "r"(a2), "r"(a3), "r"(b0), "r"(b1));
}
__device__ __forceinline__ void cvt_hilo(float2 f, unsigned &hi, unsigned &lo){
    __nv_bfloat162 h = __float22bfloat162_rn(f);
    float2 fh = __bfloat1622float2(h);
    __nv_bfloat162 l = __float22bfloat162_rn(make_float2(f.x - fh.x, f.y - fh.y));
    hi = *(unsigned*)&h; lo = *(unsigned*)&l;
}

// ---------------- K1: layernorm ----------------
__global__ void k_ln(const float* __restrict__ tf, const float* __restrict__ g,
                     const float* __restrict__ bb){
    int b = blockIdx.x, tid = threadIdx.x;
    const float* row = tf + (b*TDEC + (TDEC-1))*D;
    float x0 = row[tid], x1 = row[tid+256];
    __shared__ float s1[256], s2[256];
    s1[tid] = x0+x1; s2[tid] = x0*x0 + x1*x1;
    __syncthreads();
    for (int o=128;o;o>>=1){
        if (tid<o){ s1[tid]+=s1[tid+o]; s2[tid]+=s2[tid+o]; }
        __syncthreads();
    }
    float mu = s1[0]*(1.0f/D);
    float var = s2[0]*(1.0f/D) - mu*mu;
    float r = rsqrtf(var + 1e-5f);
    g_local_dec[b*D+tid]     = (x0-mu)*r*g[tid]     + bb[tid];
    g_local_dec[b*D+tid+256] = (x1-mu)*r*g[tid+256] + bb[tid+256];
}

// ---------------- K2: dec projections (W rows in regs, 8 batches/block) ------
__global__ void k_proj(const float* __restrict__ ua_Wp, const float* __restrict__ ua_bp,
                       const float* __restrict__ ta_Wp, const float* __restrict__ ta_bp){
    int which = blockIdx.z;
    const float* W    = which ? ta_Wp : ua_Wp;
    const float* bias = which ? ta_bp : ua_bp;
    float* outp       = which ? g_dec_ta : g_dec_ua;
    int warp = threadIdx.x >> 5, lane = threadIdx.x & 31;
    int d = blockIdx.x*8 + warp;
    const float4* wrow = (const float4*)(W + (long)d*D);
    float4 w4[4];
    #pragma unroll
    for (int i=0;i<4;i++) w4[i] = wrow[i*32 + lane];
    float bval = bias[d];
    #pragma unroll
    for (int bi=0; bi<8; bi++){
        int b = blockIdx.y*8 + bi;
        const float4* t = (const float4*)(g_local_dec + b*D);
        float acc = 0.f;
        #pragma unroll
        for (int i=0;i<4;i++){
            float4 t4 = t[i*32 + lane];
            acc += w4[i].x*t4.x + w4[i].y*t4.y + w4[i].z*t4.z + w4[i].w*t4.w;
        }
        acc = wsum(acc);
        if (!lane) outp[b*D + d] = acc + bval;
    }
}

// ---------------- K3: utterance attention + argmax + p_gen ----------------
__global__ void k_uatt(const float* __restrict__ enc, const float* __restrict__ umask,
                       const float* __restrict__ cov, const float* __restrict__ ua_wc,
                       const float* __restrict__ ua_v, const float* __restrict__ pgen_W,
                       const float* __restrict__ pgen_b,
                       float* __restrict__ o_ucov, float* __restrict__ o_pgen,
                       float* __restrict__ o_uidx){
    int b = blockIdx.x, tid = threadIdx.x;
    int warp = tid>>5, lane = tid&31;
    __shared__ float s_scores[U], s_attn[U], s_red[256];
    float4 dec4[4], wc4[4], v4[4];
    #pragma unroll
    for (int i=0;i<4;i++){
        int d = i*128 + lane*4;
        dec4[i] = *(const float4*)(g_dec_ua + b*D + d);
        wc4[i]  = *(const float4*)(ua_wc + d);
        v4[i]   = *(const float4*)(ua_v + d);
    }
    #pragma unroll
    for (int uu=0; uu<4; uu++){
        int u = warp + uu*8;
        float c = cov[b*U + u];
        const float4* e = (const float4*)(enc + (long)(b*U + u)*D);
        float acc = 0.f;
        #pragma unroll
        for (int i=0;i<4;i++){
            float4 x = e[i*32 + lane];
            acc += ftanh(x.x + dec4[i].x + c*wc4[i].x) * v4[i].x;
            acc += ftanh(x.y + dec4[i].y + c*wc4[i].y) * v4[i].y;
            acc += ftanh(x.z + dec4[i].z + c*wc4[i].z) * v4[i].z;
            acc += ftanh(x.w + dec4[i].w + c*wc4[i].w) * v4[i].w;
        }
        acc = wsum(acc);
        if (!lane) s_scores[u] = acc;
    }
    __syncthreads();
    if (warp == 0){
        int u = lane;
        float s = s_scores[u];
        float m = wmax(s);
        float e = expf(s - m);
        float den = wsum(e);
        float a_ = (e/den) * umask[b*U+u];
        float nf = wsum(a_);
        float attn = a_ / (nf == 0.f ? 1.f : nf);
        s_attn[u] = attn;
        o_ucov[b*U+u] = cov[b*U+u] + attn;
        float bv = attn; int bi = u;
        #pragma unroll
        for (int o=16;o;o>>=1){
            float ov = __shfl_xor_sync(0xffffffffu, bv, o);
            int   oi = __shfl_xor_sync(0xffffffffu, bi, o);
            if (ov > bv || (ov == bv && oi < bi)){ bv = ov; bi = oi; }
        }
        if (!lane){ g_sel[b] = bi; o_uidx[b] = (float)bi; }
    }
    __syncthreads();
    float part = 0.f;
    #pragma unroll
    for (int j=0;j<2;j++){
        int d = tid + j*256;
        float acc = 0.f;
        #pragma unroll 8
        for (int u=0;u<U;u++) acc += s_attn[u] * enc[(long)(b*U+u)*D + d];
        part += pgen_W[d]*acc + pgen_W[D + d]*g_local_dec[b*D + d];
    }
    s_red[tid] = part;
    __syncthreads();
    for (int o=128;o;o>>=1){ if (tid<o) s_red[tid]+=s_red[tid+o]; __syncthreads(); }
    if (!tid) o_pgen[b] = 1.f/(1.f + expf(-(s_red[0] + pgen_b[0])));
}

// ---------------- K4: token attention (R5 exact: 4-stage ring, wait_group 3) --
__global__ void __launch_bounds__(256,3)
k_tatt(const float* __restrict__ tok, const float* __restrict__ tmask,
       const float* __restrict__ tcov, const float* __restrict__ ta_wc,
       const float* __restrict__ ta_v,
       float* __restrict__ o_ntc, float* __restrict__ o_tattn){
    extern __shared__ float ring[];   // 8 warps * 4 stages * 512 floats = 64KB
    __shared__ float s_scores[TK], s_attn[TK], s_cov[TK];
    int u = blockIdx.x, b = blockIdx.y;
    int tid = threadIdx.x, warp = tid>>5, lane = tid&31;
    int ub = u*B + b;
    float* wring = ring + warp*2048;
    unsigned rb = smem_u32(wring);
    const float* rowbase = tok + (long)ub*TK*D;
    if (tid < TK) s_cov[tid] = tcov[ub*TK + tid];

    float4 dec4[4], wc4[4], v4[4];
    #pragma unroll
    for (int i=0;i<4;i++){
        int d = i*128 + lane*4;
        dec4[i] = *(const float4*)(g_dec_ta + b*D + d);
        wc4[i]  = *(const float4*)(ta_wc + d);
        v4[i]   = *(const float4*)(ta_v + d);
    }
    #pragma unroll
    for (int s=0;s<3;s++){
        const float* src = rowbase + (warp*8+s)*D;
        #pragma unroll
        for (int i=0;i<4;i++)
            CPA(rb + (unsigned)(s*512 + (i*32+lane)*4)*4u, src + (i*32+lane)*4);
        CPC();
    }
    __syncthreads();   // s_cov ready
    #pragma unroll
    for (int tt=0; tt<8; tt++){
        if (tt < 5){
            const float* src = rowbase + (warp*8+tt+3)*D;
            int s = (tt+3)&3;
            #pragma unroll
            for (int i=0;i<4;i++)
                CPA(rb + (unsigned)(s*512 + (i*32+lane)*4)*4u, src + (i*32+lane)*4);
        }
        CPC();
        CPW3();
        float c = s_cov[warp*8+tt];
        const float4* xs = (const float4*)(wring + (tt&3)*512);
        float acc = 0.f;
        #pragma unroll
        for (int i=0;i<4;i++){
            float4 x = xs[i*32+lane];
            acc += ftanh(x.x + dec4[i].x + c*wc4[i].x)*v4[i].x;
            acc += ftanh(x.y + dec4[i].y + c*wc4[i].y)*v4[i].y;
            acc += ftanh(x.z + dec4[i].z + c*wc4[i].z)*v4[i].z;
            acc += ftanh(x.w + dec4[i].w + c*wc4[i].w)*v4[i].w;
        }
        acc = wsum(acc);
        if (!lane) s_scores[warp*8+tt] = acc;
    }
    __syncthreads();
    int sel = g_sel[b];
    if (warp == 0){
        float s0 = s_scores[lane], s1 = s_scores[lane+32];
        float m = wmax(fmaxf(s0,s1));
        float e0 = expf(s0-m), e1 = expf(s1-m);
        float den = wsum(e0+e1);
        float a0 = (e0/den)*tmask[ub*TK+lane];
        float a1 = (e1/den)*tmask[ub*TK+lane+32];
        float nf = wsum(a0+a1);
        float inv = 1.f/((nf==0.f)?1.f:nf);
        a0 *= inv; a1 *= inv;
        s_attn[lane] = a0; s_attn[lane+32] = a1;
        o_ntc[ub*TK+lane]    = s_cov[lane]    + a0;
        o_ntc[ub*TK+lane+32] = s_cov[lane+32] + a1;
        if (u == sel){ o_tattn[b*TK+lane] = a0; o_tattn[b*TK+lane+32] = a1; }
    }
    __syncthreads();
    if (u == sel){
        #pragma unroll
        for (int j=0;j<2;j++){
            int d = tid + j*256;
            float acc = 0.f;
            #pragma unroll 8
            for (int t=0;t<TK;t++) acc += s_attn[t]*tok[(long)ub*TK*D + t*D + d];
            g_target_out[b*D + d] = acc;
        }
    }
}

// ---------------- K5: h -> bf16 hi/lo (W1 rows in regs, 8 batches/block) -----
__global__ void k_h(const float* __restrict__ W1, const float* __restrict__ b1){
    int warp = threadIdx.x>>5, lane = threadIdx.x&31;
    int d = blockIdx.x*8 + warp;
    const float4* w = (const float4*)(W1 + (long)d*2*D);
    float4 w4[8];
    #pragma unroll
    for (int i=0;i<8;i++) w4[i] = w[i*32+lane];
    float bval = b1[d];
    #pragma unroll
    for (int bi=0; bi<8; bi++){
        int b = blockIdx.y*8 + bi;
        const float4* t0 = (const float4*)(g_target_out + b*D);
        const float4* t1 = (const float4*)(g_local_dec + b*D);
        float acc=0.f;
        #pragma unroll
        for (int i=0;i<4;i++){
            float4 x = t0[i*32+lane];
            acc += w4[i].x*x.x + w4[i].y*x.y + w4[i].z*x.z + w4[i].w*x.w;
        }
        #pragma unroll
        for (int i=0;i<4;i++){
            float4 x = t1[i*32+lane];
            acc += w4[i+4].x*x.x + w4[i+4].y*x.y + w4[i+4].z*x.z + w4[i+4].w*x.w;
        }
        acc = wsum(acc);
        if (!lane){
            float h = acc + bval;
            __nv_bfloat16 hi = __float2bfloat16(h);
            __nv_bfloat16 lo = __float2bfloat16(h - __bfloat162float(hi));
            ((__nv_bfloat16*)g_hhi)[b*512 + d] = hi;
            ((__nv_bfloat16*)g_hlo)[b*512 + d] = lo;
        }
    }
}

// ---------------- K5b: pack B fragments as uint4 pairs ----------------
__global__ void k_pack(){
    int i = blockIdx.x*256 + threadIdx.x;      // 0..4095
    int n = i >> 7, j = i & 127;
    int kc = j >> 2, tg = j & 3;
    int kp = n*256 + kc*8 + tg;
    g_hp[i] = make_uint4(g_hhi[kp], g_hlo[kp], g_hhi[kp+4], g_hlo[kp+4]);
}

// ---------------- K6: vocab GEMM (per-warp 5-stage cp.async W; B via L2 LDG) --
#define WNST 5                   // stages per warp
#define WSTGF 256                // floats per stage (16 rows x 16 floats, swizzled)
#define VOC_SMEM (8*WNST*WSTGF*4)   // 40960 B
__global__ void __launch_bounds__(256,3)
k_vocab(const float* __restrict__ W2, const float* __restrict__ b2){
    extern __shared__ char smraw[];
    float* sW = (float*)smraw;                        // 8 warps x 5 stages x 1KB
    __shared__ float sm_m[8][32], sm_s[8][32];
    int tid = threadIdx.x, wm = tid>>5, lane = tid&31;
    int g = lane>>2, tg = lane&3;
    long v0 = (long)blockIdx.x * 128;

    // per-warp W staging: warp wm owns rows [wm*16, +16); lane stages 2 x 16B chunks
    // swizzled layout within a 1KB stage: phys_chunk = c4 ^ (row & 3)
    int idx0 = lane*2, idx1 = lane*2+1;
    int row0 = idx0>>2, c40 = idx0&3;
    int row1 = idx1>>2, c41 = idx1&3;
    long gv0 = v0 + wm*16 + row0; if (gv0 >= V) gv0 = V-1;
    long gv1 = v0 + wm*16 + row1; if (gv1 >= V) gv1 = V-1;
    const float* src0 = W2 + gv0*D + c40*4;
    const float* src1 = W2 + gv1*D + c41*4;
    float* wbase = sW + wm*WNST*WSTGF;
    unsigned sb = smem_u32(wbase);
    unsigned dst0 = sb + (unsigned)(row0*64 + ((c40 ^ (row0&3))*16));
    unsigned dst1 = sb + (unsigned)(row1*64 + ((c41 ^ (row1&3))*16));

    // prologue: W chunks 0..3 -> stages 0..3 (per-warp groups 0..3)
    #pragma unroll
    for (int s=0; s<4; s++){
        CPA(dst0 + (unsigned)s*1024u, src0 + s*16);
        CPA(dst1 + (unsigned)s*1024u, src1 + s*16);
        CPC();
    }

    float dd[4][4];
    #pragma unroll
    for (int nt=0;nt<4;nt++){ dd[nt][0]=dd[nt][1]=dd[nt][2]=dd[nt][3]=0.f; }

    // fragment read offsets within a (swizzled) stage
    int r3 = g & 3;
    int o_lo = ((tg>>1) ^ r3)*4 + (tg&1)*2;         // cols tg*2   (chunk tg>>1)
    int o_hi = (((tg>>1)|2) ^ r3)*4 + (tg&1)*2;     // cols tg*2+8 (chunk 2+(tg>>1))
    int rA = g*16, rB = (g+8)*16;

    // B fragment pointers: g_hp[(nt*8+g)*128 + kc*4 + tg]
    const uint4* hp = g_hp + (long)g*128 + tg;
    uint4 bu[4];
    #pragma unroll
    for (int nt=0; nt<4; nt++) bu[nt] = hp[(long)nt*8*128];   // kc=0

    for (int kc=0; kc<32; kc++){
        CPW3();   // per-warp W groups 0..kc complete -> chunk kc resident
        if (kc+4 < 32){
            unsigned st = (unsigned)((kc+4)%WNST)*1024u;
            CPA(dst0 + st, src0 + (kc+4)*16);
            CPA(dst1 + st, src1 + (kc+4)*16);
        }
        CPC();    // unconditional: exactly one group per iteration

        const float* sw = wbase + (kc%WNST)*WSTGF;
        float2 fa0 = *(const float2*)(sw + rA + o_lo);
        float2 fa1 = *(const float2*)(sw + rB + o_lo);
        float2 fa2 = *(const float2*)(sw + rA + o_hi);
        float2 fa3 = *(const float2*)(sw + rB + o_hi);

        unsigned ah0,al0,ah1,al1,ah2,al2,ah3,al3;
        cvt_hilo(fa0, ah0, al0);
        cvt_hilo(fa1, ah1, al1);
        cvt_hilo(fa2, ah2, al2);
        cvt_hilo(fa3, ah3, al3);

        uint4 bc[4];
        #pragma unroll
        for (int nt=0; nt<4; nt++) bc[nt] = bu[nt];
        if (kc+1 < 32){
            const uint4* hpn = hp + (kc+1)*4;
            #pragma unroll
            for (int nt=0; nt<4; nt++) bu[nt] = hpn[(long)nt*8*128];
        }

        #pragma unroll
        for (int nt=0; nt<4; nt++){
            mma16816(dd[nt], ah0, ah1, ah2, ah3, bc[nt].x, bc[nt].z);  // hi*hi
            mma16816(dd[nt], al0, al1, al2, al3, bc[nt].x, bc[nt].z);  // lo*hi
            mma16816(dd[nt], ah0, ah1, ah2, ah3, bc[nt].y, bc[nt].w);  // hi*lo
        }
    }

    long rr0 = v0 + wm*16 + g;
    long rr1 = rr0 + 8;
    bool ok0 = (rr0 < V), ok1 = (rr1 < V);
    float bias0 = ok0 ? b2[rr0] : 0.f;
    float bias1 = ok1 ? b2[rr1] : 0.f;
    #pragma unroll
    for (int nt=0; nt<4; nt++){
        int n = nt*8 + tg*2;
        if (ok0){
            g_logits[(long)n*V + rr0]     = dd[nt][0] + bias0;
            g_logits[(long)(n+1)*V + rr0] = dd[nt][1] + bias0;
        }
        if (ok1){
            g_logits[(long)n*V + rr1]     = dd[nt][2] + bias1;
            g_logits[(long)(n+1)*V + rr1] = dd[nt][3] + bias1;
        }
    }

    // ---- fused partial softmax stats: per (block, n) (max, sumexp) ----
    #pragma unroll
    for (int nt=0; nt<4; nt++){
        #pragma unroll
        for (int p=0; p<2; p++){
            float x0 = ok0 ? dd[nt][p]   + bias0 : -1e30f;
            float x1 = ok1 ? dd[nt][p+2] + bias1 : -1e30f;
            float m = fmaxf(x0, x1);
            #pragma unroll
            for (int o=4; o<32; o<<=1) m = fmaxf(m, __shfl_xor_sync(0xffffffffu, m, o));
            float s = (ok0 ? expf(x0 - m) : 0.f) + (ok1 ? expf(x1 - m) : 0.f);
            #pragma unroll
            for (int o=4; o<32; o<<=1) s += __shfl_xor_sync(0xffffffffu, s, o);
            if (g == 0){
                int n = nt*8 + tg*2 + p;
                sm_m[wm][n] = m;
                sm_s[wm][n] = s;
            }
        }
    }
    __syncthreads();
    if (wm == 0){
        float M = -1e30f;
        #pragma unroll
        for (int w=0; w<8; w++) M = fmaxf(M, sm_m[w][lane]);
        float S = 0.f;
        #pragma unroll
        for (int w=0; w<8; w++) S += sm_s[w][lane] * expf(sm_m[w][lane] - M);
        g_pm[(long)lane*512 + blockIdx.x] = M;
        g_ps[(long)lane*512 + blockIdx.x] = S;
    }
}

// ---------------- K7: combine partial stats (tiny) ----------------
__global__ void k_red(){
    int b = blockIdx.x, tid = threadIdx.x;
    __shared__ float smm[256], sms[256];
    float m0 = (tid      < NVBLK) ? g_pm[(long)b*512 + tid]       : -1e30f;
    float s0 = (tid      < NVBLK) ? g_ps[(long)b*512 + tid]       : 0.f;
    float m1 = (tid+256  < NVBLK) ? g_pm[(long)b*512 + tid + 256] : -1e30f;
    float s1 = (tid+256  < NVBLK) ? g_ps[(long)b*512 + tid + 256] : 0.f;
    float m = fmaxf(m0, m1);
    smm[tid] = m;
    __syncthreads();
    for (int o=128;o;o>>=1){ if (tid<o) smm[tid]=fmaxf(smm[tid],smm[tid+o]); __syncthreads(); }
    float M = smm[0];
    __syncthreads();
    float s = s0*expf(m0 - M) + s1*expf(m1 - M);
    sms[tid] = s;
    __syncthreads();
    for (int o=128;o;o>>=1){ if (tid<o) sms[tid]+=sms[tid+o]; __syncthreads(); }
    if (!tid){ g_m[b] = M; g_inv_s[b] = 1.f/sms[0]; }
}

// ---------------- K8: vocab_dist ----------------
__global__ void k_soft(float* __restrict__ o_vocab){
    long i = (long)blockIdx.x*256 + threadIdx.x;
    if (i >= (long)B*V) return;
    int b = (int)(i / V);
    o_vocab[i] = expf(g_logits[i] - g_m[b]) * g_inv_s[b];
}

// ---------------- launch ----------------
extern "C" void kernel_launch(void* const* d_in, const int* in_sizes, int n_in,
                              void* d_out, int out_size){
    const float* tf    = (const float*)d_in[0];
    const float* enc   = (const float*)d_in[2];
    const float* umask = (const float*)d_in[3];
    const float* tok   = (const float*)d_in[4];
    const float* tmask = (const float*)d_in[5];
    const float* cov   = (const float*)d_in[6];
    const float* tcov  = (const float*)d_in[7];
    const float* ua_Wp = (const float*)d_in[8];
    const float* ua_bp = (const float*)d_in[9];
    const float* ua_v  = (const float*)d_in[10];
    const float* ua_wc = (const float*)d_in[11];
    const float* ta_Wp = (const float*)d_in[12];
    const float* ta_bp = (const float*)d_in[13];
    const float* ta_v  = (const float*)d_in[14];
    const float* ta_wc = (const float*)d_in[15];
    const float* pgen_W= (const float*)d_in[16];
    const float* pgen_b= (const float*)d_in[17];
    const float* W1    = (const float*)d_in[18];
    const float* b1    = (const float*)d_in[19];
    const float* W2    = (const float*)d_in[20];
    const float* b2    = (const float*)d_in[21];
    const float* ln_g  = (const float*)d_in[22];
    const float* ln_b  = (const float*)d_in[23];

    float* out = (float*)d_out;
    float* o_vocab = out;
    float* o_tattn = o_vocab + (long)B*V;
    float* o_pgen  = o_tattn + B*TK;
    float* o_ucov  = o_pgen + B;
    float* o_ntc   = o_ucov + B*U;
    float* o_uidx  = o_ntc + (long)U*B*TK;

    cudaFuncSetAttribute(k_tatt, cudaFuncAttributeMaxDynamicSharedMemorySize, 65536);
    cudaFuncSetAttribute(k_vocab, cudaFuncAttributeMaxDynamicSharedMemorySize, VOC_SMEM);

    k_ln   <<<B, 256>>>(tf, ln_g, ln_b);
    k_proj <<<dim3(D/8, B/8, 2), 256>>>(ua_Wp, ua_bp, ta_Wp, ta_bp);
    k_uatt <<<B, 256>>>(enc, umask, cov, ua_wc, ua_v, pgen_W, pgen_b,
                        o_ucov, o_pgen, o_uidx);
    k_tatt <<<dim3(U, B), 256, 65536>>>(tok, tmask, tcov, ta_wc, ta_v, o_ntc, o_tattn);
    k_h    <<<dim3(D/8, B/8), 256>>>(W1, b1);
    k_pack <<<16, 256>>>();
    k_vocab<<<NVBLK, 256, VOC_SMEM>>>(W2, b2);
    k_red  <<<B, 256>>>();
    k_soft <<<(int)(((long)B*V + 255)/256), 256>>>(o_vocab);
}

// round 14
// speedup vs baseline: 1.2226x; 1.0431x over previous
#include <cuda_runtime.h>
#include <cuda_bf16.h>

#define B   32
#define U   32
#define TK  64
#define TDEC 64
#define D   512
#define V   50257
#define NVBLK 393     // (V+127)/128

// ---------------- scratch ----------------
__device__ float g_local_dec[B*D];
__device__ float g_dec_ua[B*D];
__device__ float g_dec_ta[B*D];
__device__ float g_target_out[B*D];
__device__ int   g_sel[B];
__device__ float g_logits[(long)B*V];
__device__ float g_m[B];
__device__ float g_inv_s[B];
__device__ unsigned g_hhi[B*256];   // [b][kpair] bf16x2 of h_hi
__device__ unsigned g_hlo[B*256];   // [b][kpair] bf16x2 of h_lo
__device__ uint4 g_hp[B*128];       // [b][kc*4+tg] = {hi[kp], lo[kp], hi[kp+4], lo[kp+4]}
__device__ float g_pm[B*512];       // per-(b, vblock) partial max
__device__ float g_ps[B*512];       // per-(b, vblock) partial sumexp

// ---------------- helpers ----------------
__device__ __forceinline__ float ftanh(float x){
    float y; asm("tanh.approx.f32 %0, %1;" : "=f"(y) : "f"(x)); return y;
}
__device__ __forceinline__ float wsum(float v){
    #pragma unroll
    for (int o=16;o;o>>=1) v += __shfl_xor_sync(0xffffffffu, v, o);
    return v;
}
__device__ __forceinline__ float wmax(float v){
    #pragma unroll
    for (int o=16;o;o>>=1) v = fmaxf(v, __shfl_xor_sync(0xffffffffu, v, o));
    return v;
}
__device__ __forceinline__ unsigned smem_u32(const void* p){
    unsigned a;
    asm("{ .reg .u64 t; cvta.to.shared.u64 t, %1; cvt.u32.u64 %0, t; }" : "=r"(a) : "l"(p));
    return a;
}

// cp.async
#define CPA(dst, src) asm volatile("cp.async.cg.shared.global [%0], [%1], 16;" :: "r"(dst), "l"(src) : "memory")
#define CPC()  asm volatile("cp.async.commit_group;" ::: "memory")
#define CPW3() asm volatile("cp.async.wait_group 3;" ::: "memory")

// bf16 mma m16n8k16
__device__ __forceinline__ void mma16816(float* d, unsigned a0, unsigned a1,
                                         unsigned a2, unsigned a3,
                                         unsigned b0, unsigned b1){
    asm volatile("mma.sync.aligned.m16n8k16.row.col.f32.bf16.bf16.f32 "
        "{%0,%1,%2,%3}, {%4,%5,%6,%7}, {%8,%9}, {%0,%1,%2,%3};"
        : "+f"(d[0]), "+f"(d[1]), "+f"(d[2]), "+f"(d[3])
        : "r"(a0), "r"(a1), "r"(a2), "r"(a3), "r"(b0), "r"(b1));
}
__device__ __forceinline__ void cvt_hilo(float2 f, unsigned &hi, unsigned &lo){
    __nv_bfloat162 h = __float22bfloat162_rn(f);
    float2 fh = __bfloat1622float2(h);
    __nv_bfloat162 l = __float22bfloat162_rn(make_float2(f.x - fh.x, f.y - fh.y));
    hi = *(unsigned*)&h; lo = *(unsigned*)&l;
}

// ---------------- K1: layernorm ----------------
__global__ void k_ln(const float* __restrict__ tf, const float* __restrict__ g,
                     const float* __restrict__ bb){
    int b = blockIdx.x, tid = threadIdx.x;
    const float* row = tf + (b*TDEC + (TDEC-1))*D;
    float x0 = row[tid], x1 = row[tid+256];
    __shared__ float s1[256], s2[256];
    s1[tid] = x0+x1; s2[tid] = x0*x0 + x1*x1;
    __syncthreads();
    for (int o=128;o;o>>=1){
        if (tid<o){ s1[tid]+=s1[tid+o]; s2[tid]+=s2[tid+o]; }
        __syncthreads();
    }
    float mu = s1[0]*(1.0f/D);
    float var = s2[0]*(1.0f/D) - mu*mu;
    float r = rsqrtf(var + 1e-5f);
    g_local_dec[b*D+tid]     = (x0-mu)*r*g[tid]     + bb[tid];
    g_local_dec[b*D+tid+256] = (x1-mu)*r*g[tid+256] + bb[tid+256];
}

// ---------------- K2: dec projections ----------------
__global__ void k_proj(const float* __restrict__ ua_Wp, const float* __restrict__ ua_bp,
                       const float* __restrict__ ta_Wp, const float* __restrict__ ta_bp){
    int which = blockIdx.z;
    const float* W    = which ? ta_Wp : ua_Wp;
    const float* bias = which ? ta_bp : ua_bp;
    float* outp       = which ? g_dec_ta : g_dec_ua;
    int warp = threadIdx.x >> 5, lane = threadIdx.x & 31;
    int d = blockIdx.x*8 + warp;
    const float4* wrow = (const float4*)(W + (long)d*D);
    float4 w4[4];
    #pragma unroll
    for (int i=0;i<4;i++) w4[i] = wrow[i*32 + lane];
    float bval = bias[d];
    #pragma unroll
    for (int bi=0; bi<8; bi++){
        int b = blockIdx.y*8 + bi;
        const float4* t = (const float4*)(g_local_dec + b*D);
        float acc = 0.f;
        #pragma unroll
        for (int i=0;i<4;i++){
            float4 t4 = t[i*32 + lane];
            acc += w4[i].x*t4.x + w4[i].y*t4.y + w4[i].z*t4.z + w4[i].w*t4.w;
        }
        acc = wsum(acc);
        if (!lane) outp[b*D + d] = acc + bval;
    }
}

// ---------------- K3: utterance attention + argmax + p_gen ----------------
__global__ void k_uatt(const float* __restrict__ enc, const float* __restrict__ umask,
                       const float* __restrict__ cov, const float* __restrict__ ua_wc,
                       const float* __restrict__ ua_v, const float* __restrict__ pgen_W,
                       const float* __restrict__ pgen_b,
                       float* __restrict__ o_ucov, float* __restrict__ o_pgen,
                       float* __restrict__ o_uidx){
    int b = blockIdx.x, tid = threadIdx.x;
    int warp = tid>>5, lane = tid&31;
    __shared__ float s_scores[U], s_attn[U], s_red[256];
    float4 dec4[4], wc4[4], v4[4];
    #pragma unroll
    for (int i=0;i<4;i++){
        int d = i*128 + lane*4;
        dec4[i] = *(const float4*)(g_dec_ua + b*D + d);
        wc4[i]  = *(const float4*)(ua_wc + d);
        v4[i]   = *(const float4*)(ua_v + d);
    }
    #pragma unroll
    for (int uu=0; uu<4; uu++){
        int u = warp + uu*8;
        float c = cov[b*U + u];
        const float4* e = (const float4*)(enc + (long)(b*U + u)*D);
        float acc = 0.f;
        #pragma unroll
        for (int i=0;i<4;i++){
            float4 x = e[i*32 + lane];
            acc += ftanh(x.x + dec4[i].x + c*wc4[i].x) * v4[i].x;
            acc += ftanh(x.y + dec4[i].y + c*wc4[i].y) * v4[i].y;
            acc += ftanh(x.z + dec4[i].z + c*wc4[i].z) * v4[i].z;
            acc += ftanh(x.w + dec4[i].w + c*wc4[i].w) * v4[i].w;
        }
        acc = wsum(acc);
        if (!lane) s_scores[u] = acc;
    }
    __syncthreads();
    if (warp == 0){
        int u = lane;
        float s = s_scores[u];
        float m = wmax(s);
        float e = expf(s - m);
        float den = wsum(e);
        float a_ = (e/den) * umask[b*U+u];
        float nf = wsum(a_);
        float attn = a_ / (nf == 0.f ? 1.f : nf);
        s_attn[u] = attn;
        o_ucov[b*U+u] = cov[b*U+u] + attn;
        float bv = attn; int bi = u;
        #pragma unroll
        for (int o=16;o;o>>=1){
            float ov = __shfl_xor_sync(0xffffffffu, bv, o);
            int   oi = __shfl_xor_sync(0xffffffffu, bi, o);
            if (ov > bv || (ov == bv && oi < bi)){ bv = ov; bi = oi; }
        }
        if (!lane){ g_sel[b] = bi; o_uidx[b] = (float)bi; }
    }
    __syncthreads();
    float part = 0.f;
    #pragma unroll
    for (int j=0;j<2;j++){
        int d = tid + j*256;
        float acc = 0.f;
        #pragma unroll 8
        for (int u=0;u<U;u++) acc += s_attn[u] * enc[(long)(b*U+u)*D + d];
        part += pgen_W[d]*acc + pgen_W[D + d]*g_local_dec[b*D + d];
    }
    s_red[tid] = part;
    __syncthreads();
    for (int o=128;o;o>>=1){ if (tid<o) s_red[tid]+=s_red[tid+o]; __syncthreads(); }
    if (!tid) o_pgen[b] = 1.f/(1.f + expf(-(s_red[0] + pgen_b[0])));
}

// ---------------- shared device body: token attention for one (u,b) tile ------
__device__ __forceinline__ void tatt_tile(
    const float* __restrict__ tok, const float* __restrict__ tmask,
    const float* __restrict__ tcov, const float* __restrict__ ta_wc,
    const float* __restrict__ ta_v, float* __restrict__ o_ntc,
    float* __restrict__ o_tattn, float* ring,
    float* s_scores, float* s_attn, float* s_cov,
    int u, int b, bool is_sel)
{
    int tid = threadIdx.x, warp = tid>>5, lane = tid&31;
    int ub = u*B + b;
    float* wring = ring + warp*2048;
    unsigned rb = smem_u32(wring);
    const float* rowbase = tok + (long)ub*TK*D;
    if (tid < TK) s_cov[tid] = tcov[ub*TK + tid];

    float4 dec4[4], wc4[4], v4[4];
    #pragma unroll
    for (int i=0;i<4;i++){
        int d = i*128 + lane*4;
        dec4[i] = *(const float4*)(g_dec_ta + b*D + d);
        wc4[i]  = *(const float4*)(ta_wc + d);
        v4[i]   = *(const float4*)(ta_v + d);
    }
    #pragma unroll
    for (int s=0;s<3;s++){
        const float* src = rowbase + (warp*8+s)*D;
        #pragma unroll
        for (int i=0;i<4;i++)
            CPA(rb + (unsigned)(s*512 + (i*32+lane)*4)*4u, src + (i*32+lane)*4);
        CPC();
    }
    __syncthreads();   // s_cov ready
    #pragma unroll
    for (int tt=0; tt<8; tt++){
        if (tt < 5){
            const float* src = rowbase + (warp*8+tt+3)*D;
            int s = (tt+3)&3;
            #pragma unroll
            for (int i=0;i<4;i++)
                CPA(rb + (unsigned)(s*512 + (i*32+lane)*4)*4u, src + (i*32+lane)*4);
        }
        CPC();
        CPW3();
        float c = s_cov[warp*8+tt];
        const float4* xs = (const float4*)(wring + (tt&3)*512);
        float acc = 0.f;
        #pragma unroll
        for (int i=0;i<4;i++){
            float4 x = xs[i*32+lane];
            acc += ftanh(x.x + dec4[i].x + c*wc4[i].x)*v4[i].x;
            acc += ftanh(x.y + dec4[i].y + c*wc4[i].y)*v4[i].y;
            acc += ftanh(x.z + dec4[i].z + c*wc4[i].z)*v4[i].z;
            acc += ftanh(x.w + dec4[i].w + c*wc4[i].w)*v4[i].w;
        }
        acc = wsum(acc);
        if (!lane) s_scores[warp*8+tt] = acc;
    }
    __syncthreads();
    if (warp == 0){
        float s0 = s_scores[lane], s1 = s_scores[lane+32];
        float m = wmax(fmaxf(s0,s1));
        float e0 = expf(s0-m), e1 = expf(s1-m);
        float den = wsum(e0+e1);
        float a0 = (e0/den)*tmask[ub*TK+lane];
        float a1 = (e1/den)*tmask[ub*TK+lane+32];
        float nf = wsum(a0+a1);
        float inv = 1.f/((nf==0.f)?1.f:nf);
        a0 *= inv; a1 *= inv;
        s_attn[lane] = a0; s_attn[lane+32] = a1;
        o_ntc[ub*TK+lane]    = s_cov[lane]    + a0;
        o_ntc[ub*TK+lane+32] = s_cov[lane+32] + a1;
        if (is_sel){ o_tattn[b*TK+lane] = a0; o_tattn[b*TK+lane+32] = a1; }
    }
    __syncthreads();
    if (is_sel){
        #pragma unroll
        for (int j=0;j<2;j++){
            int d = tid + j*256;
            float acc = 0.f;
            #pragma unroll 8
            for (int t=0;t<TK;t++) acc += s_attn[t]*tok[(long)ub*TK*D + t*D + d];
            g_target_out[b*D + d] = acc;
        }
    }
}

// ---------------- K4a: selected-tile token attention (32 blocks) -------------
__global__ void __launch_bounds__(256,3)
k_tatt_sel(const float* __restrict__ tok, const float* __restrict__ tmask,
           const float* __restrict__ tcov, const float* __restrict__ ta_wc,
           const float* __restrict__ ta_v,
           float* __restrict__ o_ntc, float* __restrict__ o_tattn){
    extern __shared__ float ring[];
    __shared__ float s_scores[TK], s_attn[TK], s_cov[TK];
    int b = blockIdx.x;
    int u = g_sel[b];
    tatt_tile(tok, tmask, tcov, ta_wc, ta_v, o_ntc, o_tattn,
              ring, s_scores, s_attn, s_cov, u, b, true);
}

// ---------------- K5: h -> bf16 hi/lo ----------------
__global__ void k_h(const float* __restrict__ W1, const float* __restrict__ b1){
    int warp = threadIdx.x>>5, lane = threadIdx.x&31;
    int d = blockIdx.x*8 + warp;
    const float4* w = (const float4*)(W1 + (long)d*2*D);
    float4 w4[8];
    #pragma unroll
    for (int i=0;i<8;i++) w4[i] = w[i*32+lane];
    float bval = b1[d];
    #pragma unroll
    for (int bi=0; bi<8; bi++){
        int b = blockIdx.y*8 + bi;
        const float4* t0 = (const float4*)(g_target_out + b*D);
        const float4* t1 = (const float4*)(g_local_dec + b*D);
        float acc=0.f;
        #pragma unroll
        for (int i=0;i<4;i++){
            float4 x = t0[i*32+lane];
            acc += w4[i].x*x.x + w4[i].y*x.y + w4[i].z*x.z + w4[i].w*x.w;
        }
        #pragma unroll
        for (int i=0;i<4;i++){
            float4 x = t1[i*32+lane];
            acc += w4[i+4].x*x.x + w4[i+4].y*x.y + w4[i+4].z*x.z + w4[i+4].w*x.w;
        }
        acc = wsum(acc);
        if (!lane){
            float h = acc + bval;
            __nv_bfloat16 hi = __float2bfloat16(h);
            __nv_bfloat16 lo = __float2bfloat16(h - __bfloat162float(hi));
            ((__nv_bfloat16*)g_hhi)[b*512 + d] = hi;
            ((__nv_bfloat16*)g_hlo)[b*512 + d] = lo;
        }
    }
}

// ---------------- K5b: pack B fragments as uint4 pairs ----------------
__global__ void k_pack(){
    int i = blockIdx.x*256 + threadIdx.x;      // 0..4095
    int n = i >> 7, j = i & 127;
    int kc = j >> 2, tg = j & 3;
    int kp = n*256 + kc*8 + tg;
    g_hp[i] = make_uint4(g_hhi[kp], g_hlo[kp], g_hhi[kp+4], g_hlo[kp+4]);
}

// ---------------- K6: FUSED vocab GEMM + remaining token attention -----------
#define WNST 5
#define WSTGF 256
#define MAIN_SMEM 65536
__global__ void __launch_bounds__(256,3)
k_main(const float* __restrict__ W2, const float* __restrict__ b2,
       const float* __restrict__ tok, const float* __restrict__ tmask,
       const float* __restrict__ tcov, const float* __restrict__ ta_wc,
       const float* __restrict__ ta_v,
       float* __restrict__ o_ntc, float* __restrict__ o_tattn){
    extern __shared__ char smraw[];
    __shared__ float sm_m[8][32], sm_s[8][32];
    __shared__ float s_scores[TK], s_attn[TK], s_cov[TK];
    int tid = threadIdx.x, wm = tid>>5, lane = tid&31;

    if (blockIdx.x >= NVBLK){
        // ------- token attention path -------
        int idx = blockIdx.x - NVBLK;
        int u = idx >> 5, b = idx & 31;
        if (u == g_sel[b]) return;   // done by k_tatt_sel
        tatt_tile(tok, tmask, tcov, ta_wc, ta_v, o_ntc, o_tattn,
                  (float*)smraw, s_scores, s_attn, s_cov, u, b, false);
        return;
    }

    // ------- vocab GEMM path -------
    float* sW = (float*)smraw;                        // 8 warps x 5 stages x 1KB
    int g = lane>>2, tg = lane&3;
    long v0 = (long)blockIdx.x * 128;

    int idx0 = lane*2, idx1 = lane*2+1;
    int row0 = idx0>>2, c40 = idx0&3;
    int row1 = idx1>>2, c41 = idx1&3;
    long gv0 = v0 + wm*16 + row0; if (gv0 >= V) gv0 = V-1;
    long gv1 = v0 + wm*16 + row1; if (gv1 >= V) gv1 = V-1;
    const float* src0 = W2 + gv0*D + c40*4;
    const float* src1 = W2 + gv1*D + c41*4;
    float* wbase = sW + wm*WNST*WSTGF;
    unsigned sb = smem_u32(wbase);
    unsigned dst0 = sb + (unsigned)(row0*64 + ((c40 ^ (row0&3))*16));
    unsigned dst1 = sb + (unsigned)(row1*64 + ((c41 ^ (row1&3))*16));

    #pragma unroll
    for (int s=0; s<4; s++){
        CPA(dst0 + (unsigned)s*1024u, src0 + s*16);
        CPA(dst1 + (unsigned)s*1024u, src1 + s*16);
        CPC();
    }

    float dd[4][4];
    #pragma unroll
    for (int nt=0;nt<4;nt++){ dd[nt][0]=dd[nt][1]=dd[nt][2]=dd[nt][3]=0.f; }

    int r3 = g & 3;
    int o_lo = ((tg>>1) ^ r3)*4 + (tg&1)*2;
    int o_hi = (((tg>>1)|2) ^ r3)*4 + (tg&1)*2;
    int rA = g*16, rB = (g+8)*16;
    const uint4* hp = g_hp + (long)g*128 + tg;

    for (int kc=0; kc<32; kc++){
        CPW3();
        if (kc+4 < 32){
            unsigned st = (unsigned)((kc+4)%WNST)*1024u;
            CPA(dst0 + st, src0 + (kc+4)*16);
            CPA(dst1 + st, src1 + (kc+4)*16);
        }
        CPC();

        const float* sw = wbase + (kc%WNST)*WSTGF;
        float2 fa0 = *(const float2*)(sw + rA + o_lo);
        float2 fa1 = *(const float2*)(sw + rB + o_lo);
        float2 fa2 = *(const float2*)(sw + rA + o_hi);
        float2 fa3 = *(const float2*)(sw + rB + o_hi);

        unsigned ah0,al0,ah1,al1,ah2,al2,ah3,al3;
        cvt_hilo(fa0, ah0, al0);
        cvt_hilo(fa1, ah1, al1);
        cvt_hilo(fa2, ah2, al2);
        cvt_hilo(fa3, ah3, al3);

        const uint4* hpk = hp + kc*4;
        #pragma unroll
        for (int nt=0; nt<4; nt++){
            uint4 bc = hpk[(long)nt*1024];
            mma16816(dd[nt], ah0, ah1, ah2, ah3, bc.x, bc.z);  // hi*hi
            mma16816(dd[nt], al0, al1, al2, al3, bc.x, bc.z);  // lo*hi
            mma16816(dd[nt], ah0, ah1, ah2, ah3, bc.y, bc.w);  // hi*lo
        }
    }

    long rr0 = v0 + wm*16 + g;
    long rr1 = rr0 + 8;
    bool ok0 = (rr0 < V), ok1 = (rr1 < V);
    float bias0 = ok0 ? b2[rr0] : 0.f;
    float bias1 = ok1 ? b2[rr1] : 0.f;
    #pragma unroll
    for (int nt=0; nt<4; nt++){
        int n = nt*8 + tg*2;
        if (ok0){
            g_logits[(long)n*V + rr0]     = dd[nt][0] + bias0;
            g_logits[(long)(n+1)*V + rr0] = dd[nt][1] + bias0;
        }
        if (ok1){
            g_logits[(long)n*V + rr1]     = dd[nt][2] + bias1;
            g_logits[(long)(n+1)*V + rr1] = dd[nt][3] + bias1;
        }
    }

    // fused partial softmax stats
    #pragma unroll
    for (int nt=0; nt<4; nt++){
        #pragma unroll
        for (int p=0; p<2; p++){
            float x0 = ok0 ? dd[nt][p]   + bias0 : -1e30f;
            float x1 = ok1 ? dd[nt][p+2] + bias1 : -1e30f;
            float m = fmaxf(x0, x1);
            #pragma unroll
            for (int o=4; o<32; o<<=1) m = fmaxf(m, __shfl_xor_sync(0xffffffffu, m, o));
            float s = (ok0 ? expf(x0 - m) : 0.f) + (ok1 ? expf(x1 - m) : 0.f);
            #pragma unroll
            for (int o=4; o<32; o<<=1) s += __shfl_xor_sync(0xffffffffu, s, o);
            if (g == 0){
                int n = nt*8 + tg*2 + p;
                sm_m[wm][n] = m;
                sm_s[wm][n] = s;
            }
        }
    }
    __syncthreads();
    if (wm == 0){
        float M = -1e30f;
        #pragma unroll
        for (int w=0; w<8; w++) M = fmaxf(M, sm_m[w][lane]);
        float S = 0.f;
        #pragma unroll
        for (int w=0; w<8; w++) S += sm_s[w][lane] * expf(sm_m[w][lane] - M);
        g_pm[(long)lane*512 + blockIdx.x] = M;
        g_ps[(long)lane*512 + blockIdx.x] = S;
    }
}

// ---------------- K7: combine partial stats (tiny) ----------------
__global__ void k_red(){
    int b = blockIdx.x, tid = threadIdx.x;
    __shared__ float smm[256], sms[256];
    float m0 = (tid      < NVBLK) ? g_pm[(long)b*512 + tid]       : -1e30f;
    float s0 = (tid      < NVBLK) ? g_ps[(long)b*512 + tid]       : 0.f;
    float m1 = (tid+256  < NVBLK) ? g_pm[(long)b*512 + tid + 256] : -1e30f;
    float s1 = (tid+256  < NVBLK) ? g_ps[(long)b*512 + tid + 256] : 0.f;
    float m = fmaxf(m0, m1);
    smm[tid] = m;
    __syncthreads();
    for (int o=128;o;o>>=1){ if (tid<o) smm[tid]=fmaxf(smm[tid],smm[tid+o]); __syncthreads(); }
    float M = smm[0];
    __syncthreads();
    float s = s0*expf(m0 - M) + s1*expf(m1 - M);
    sms[tid] = s;
    __syncthreads();
    for (int o=128;o;o>>=1){ if (tid<o) sms[tid]+=sms[tid+o]; __syncthreads(); }
    if (!tid){ g_m[b] = M; g_inv_s[b] = 1.f/sms[0]; }
}

// ---------------- K8: vocab_dist ----------------
__global__ void k_soft(float* __restrict__ o_vocab){
    long i = (long)blockIdx.x*256 + threadIdx.x;
    if (i >= (long)B*V) return;
    int b = (int)(i / V);
    o_vocab[i] = expf(g_logits[i] - g_m[b]) * g_inv_s[b];
}

// ---------------- launch ----------------
extern "C" void kernel_launch(void* const* d_in, const int* in_sizes, int n_in,
                              void* d_out, int out_size){
    const float* tf    = (const float*)d_in[0];
    const float* enc   = (const float*)d_in[2];
    const float* umask = (const float*)d_in[3];
    const float* tok   = (const float*)d_in[4];
    const float* tmask = (const float*)d_in[5];
    const float* cov   = (const float*)d_in[6];
    const float* tcov  = (const float*)d_in[7];
    const float* ua_Wp = (const float*)d_in[8];
    const float* ua_bp = (const float*)d_in[9];
    const float* ua_v  = (const float*)d_in[10];
    const float* ua_wc = (const float*)d_in[11];
    const float* ta_Wp = (const float*)d_in[12];
    const float* ta_bp = (const float*)d_in[13];
    const float* ta_v  = (const float*)d_in[14];
    const float* ta_wc = (const float*)d_in[15];
    const float* pgen_W= (const float*)d_in[16];
    const float* pgen_b= (const float*)d_in[17];
    const float* W1    = (const float*)d_in[18];
    const float* b1    = (const float*)d_in[19];
    const float* W2    = (const float*)d_in[20];
    const float* b2    = (const float*)d_in[21];
    const float* ln_g  = (const float*)d_in[22];
    const float* ln_b  = (const float*)d_in[23];

    float* out = (float*)d_out;
    float* o_vocab = out;
    float* o_tattn = o_vocab + (long)B*V;
    float* o_pgen  = o_tattn + B*TK;
    float* o_ucov  = o_pgen + B;
    float* o_ntc   = o_ucov + B*U;
    float* o_uidx  = o_ntc + (long)U*B*TK;

    cudaFuncSetAttribute(k_tatt_sel, cudaFuncAttributeMaxDynamicSharedMemorySize, MAIN_SMEM);
    cudaFuncSetAttribute(k_main, cudaFuncAttributeMaxDynamicSharedMemorySize, MAIN_SMEM);

    k_ln   <<<B, 256>>>(tf, ln_g, ln_b);
    k_proj <<<dim3(D/8, B/8, 2), 256>>>(ua_Wp, ua_bp, ta_Wp, ta_bp);
    k_uatt <<<B, 256>>>(enc, umask, cov, ua_wc, ua_v, pgen_W, pgen_b,
                        o_ucov, o_pgen, o_uidx);
    k_tatt_sel <<<B, 256, MAIN_SMEM>>>(tok, tmask, tcov, ta_wc, ta_v, o_ntc, o_tattn);
    k_h    <<<dim3(D/8, B/8), 256>>>(W1, b1);
    k_pack <<<16, 256>>>();
    k_main <<<NVBLK + U*B, 256, MAIN_SMEM>>>(W2, b2, tok, tmask, tcov, ta_wc, ta_v,
                                             o_ntc, o_tattn);
    k_red  <<<B, 256>>>();
    k_soft <<<(int)(((long)B*V + 255)/256), 256>>>(o_vocab);
}